// round 12
// baseline (speedup 1.0000x reference)
#include <cuda_runtime.h>
#include <cuda_fp16.h>
#include <math.h>
#include <stdint.h>

#define B_SZ 2
#define T_SZ 2048
#define HID  2048
#define NH   16
#define NKV  4
#define HD   128
#define QKV_STR 3072     // fused q|k|v row: q 0-2047, k 2048-2559, v 2560-3071

// ---------------- scratch ----------------
__device__ __half g_qkv[(size_t)B_SZ * T_SZ * QKV_STR];
__device__ __half g_attn[(size_t)B_SZ * T_SZ * HID];
__device__ __half g_xh[(size_t)B_SZ * T_SZ * HID];
__device__ __half g_wqkv_h[(size_t)QKV_STR * HID];   // rows: Wq 0-2047, Wk 2048-2559, Wv 2560-3071
__device__ __half g_wo_h[(size_t)HID * HID];
__device__ float g_cos[T_SZ * 64];
__device__ float g_sin[T_SZ * 64];

// ---------------- helpers ----------------
__device__ __forceinline__ void mma_f16(float* d, const uint32_t* a, const uint32_t* b) {
    asm volatile(
        "mma.sync.aligned.m16n8k16.row.col.f32.f16.f16.f32 "
        "{%0,%1,%2,%3}, {%4,%5,%6,%7}, {%8,%9}, {%0,%1,%2,%3};\n"
        : "+f"(d[0]), "+f"(d[1]), "+f"(d[2]), "+f"(d[3])
        : "r"(a[0]), "r"(a[1]), "r"(a[2]), "r"(a[3]), "r"(b[0]), "r"(b[1]));
}
__device__ __forceinline__ void ldsm4(uint32_t* r, uint32_t addr) {
    asm volatile("ldmatrix.sync.aligned.m8n8.x4.shared.b16 {%0,%1,%2,%3}, [%4];"
        : "=r"(r[0]), "=r"(r[1]), "=r"(r[2]), "=r"(r[3]) : "r"(addr));
}
__device__ __forceinline__ void ldsm4t(uint32_t* r, uint32_t addr) {
    asm volatile("ldmatrix.sync.aligned.m8n8.x4.trans.shared.b16 {%0,%1,%2,%3}, [%4];"
        : "=r"(r[0]), "=r"(r[1]), "=r"(r[2]), "=r"(r[3]) : "r"(addr));
}
__device__ __forceinline__ float ex2(float x) {
    float y; asm("ex2.approx.ftz.f32 %0, %1;" : "=f"(y) : "f"(x)); return y;
}
__device__ __forceinline__ uint32_t smem_u32(const void* p) {
    uint32_t a;
    asm("{ .reg .u64 t; cvta.to.shared.u64 t, %1; cvt.u32.u64 %0, t; }" : "=r"(a) : "l"(p));
    return a;
}
__device__ __forceinline__ void cpasync16(uint32_t dst, const void* src) {
    asm volatile("cp.async.cg.shared.global [%0], [%1], 16;" :: "r"(dst), "l"(src));
}
__device__ __forceinline__ void cpcommit() {
    asm volatile("cp.async.commit_group;" ::: "memory");
}
template <int N> __device__ __forceinline__ void cpwait() {
    asm volatile("cp.async.wait_group %0;" :: "n"(N) : "memory");
}
__device__ __forceinline__ uint32_t packh2(float a, float b) {
    __half2 h = __floats2half2_rn(a, b);
    return *(uint32_t*)&h;
}

// ---------------- fp32 -> fp16 conversion prepass ----------------
__global__ void conv_half(const float4* __restrict__ in, uint4* __restrict__ out, int n8) {
    int i = blockIdx.x * blockDim.x + threadIdx.x;
    if (i >= n8) return;
    float4 a = in[2 * i], b = in[2 * i + 1];
    uint4 o;
    o.x = packh2(a.x, a.y); o.y = packh2(a.z, a.w);
    o.z = packh2(b.x, b.y); o.w = packh2(b.z, b.w);
    out[i] = o;
}

// ---------------- RoPE ----------------
__global__ void build_rope_table() {
    int idx = blockIdx.x * blockDim.x + threadIdx.x;
    if (idx >= T_SZ * 64) return;
    int i = idx & 63;
    int t = idx >> 6;
    double inv_freq = pow(10000.0, -(double)i / 64.0);
    double ang = (double)t * inv_freq;
    g_cos[idx] = (float)cos(ang);
    g_sin[idx] = (float)sin(ang);
}

__global__ void rope_half(__half* __restrict__ buf, int nheads, int rowstr, float scale) {
    int idx = blockIdx.x * blockDim.x + threadIdx.x;
    int total = B_SZ * T_SZ * nheads * 64;
    if (idx >= total) return;
    int i  = idx & 63;
    int h  = (idx >> 6) % nheads;
    int bt = idx / (64 * nheads);
    int t  = bt & (T_SZ - 1);
    float c = g_cos[t * 64 + i];
    float s = g_sin[t * 64 + i];
    __half* p = buf + (size_t)bt * rowstr + h * HD + i;
    float x1 = __half2float(p[0]), x2 = __half2float(p[64]);
    p[0]  = __float2half_rn((x1 * c - x2 * s) * scale);
    p[64] = __float2half_rn((x2 * c + x1 * s) * scale);
}

// ============ fp16 mma GEMM: C[M,N] = A[M,K]*B[N,K]^T, cp.async 3-stage ============
#define HS 72
#define G_ATILE (128 * HS)
#define G_STAGE (2 * G_ATILE)
#define GEMM_SMEM (3 * G_STAGE * 2)

template <bool OUT_HALF>
__global__ void __launch_bounds__(256)
gemm_h(const __half* __restrict__ A, const __half* __restrict__ Bm,
       void* __restrict__ Cout, int N, int K) {
    extern __shared__ __half hsm[];
    const uint32_t sbase = smem_u32(hsm);
    const int tid  = threadIdx.x;
    const int lane = tid & 31, w = tid >> 5;
    const int wm = w & 1, wn = w >> 1;
    const int g = lane >> 2, tig = lane & 3;
    const int row0 = blockIdx.y * 128, col0 = blockIdx.x * 128;
    const int nchunk = K / 64;

    const int a_row_l = lane & 15, a_col_l = (lane >> 4) * 8;
    const int b_n_l = ((lane >> 4) & 1) * 8 + (lane & 7);
    const int b_k_l = ((lane >> 3) & 1) * 8;

    float acc[4][4][4];
#pragma unroll
    for (int mt = 0; mt < 4; mt++)
#pragma unroll
        for (int nt = 0; nt < 4; nt++)
#pragma unroll
            for (int j = 0; j < 4; j++) acc[mt][nt][j] = 0.f;

    auto issue = [&](int ci, int st) {
        uint32_t abuf = sbase + (uint32_t)(st * G_STAGE) * 2;
        uint32_t bbuf = abuf + G_ATILE * 2;
#pragma unroll
        for (int j = 0; j < 4; j++) {
            int s = tid + j * 256;
            int r = s >> 3, c8 = (s & 7) << 3;
            cpasync16(abuf + (uint32_t)(r * HS + c8) * 2, A + (size_t)(row0 + r) * K + ci * 64 + c8);
            cpasync16(bbuf + (uint32_t)(r * HS + c8) * 2, Bm + (size_t)(col0 + r) * K + ci * 64 + c8);
        }
        cpcommit();
    };

    issue(0, 0);
    if (nchunk > 1) issue(1, 1);
    if (nchunk > 2) issue(2, 2);

    for (int i = 0; i < nchunk; i++) {
        const int st = i % 3;
        const int ahead = nchunk - 1 - i;              // younger chunks still issued
        if (ahead >= 2)      cpwait<2>();
        else if (ahead == 1) cpwait<1>();
        else                 cpwait<0>();
        __syncthreads();

        uint32_t abuf = sbase + (uint32_t)(st * G_STAGE) * 2;
        uint32_t bbuf = abuf + G_ATILE * 2;
#pragma unroll
        for (int ks = 0; ks < 4; ks++) {
            uint32_t af[4][4];
#pragma unroll
            for (int mt = 0; mt < 4; mt++)
                ldsm4(af[mt], abuf + (uint32_t)((wm * 64 + mt * 16 + a_row_l) * HS + ks * 16 + a_col_l) * 2);
            uint32_t bf[2][4];
#pragma unroll
            for (int ntp = 0; ntp < 2; ntp++)
                ldsm4(bf[ntp], bbuf + (uint32_t)((wn * 32 + ntp * 16 + b_n_l) * HS + ks * 16 + b_k_l) * 2);
#pragma unroll
            for (int mt = 0; mt < 4; mt++)
#pragma unroll
                for (int nt = 0; nt < 4; nt++)
                    mma_f16(acc[mt][nt], af[mt], &bf[nt >> 1][(nt & 1) * 2]);
        }
        __syncthreads();
        if (i + 3 < nchunk) issue(i + 3, st);
    }

#pragma unroll
    for (int mt = 0; mt < 4; mt++) {
        int r = row0 + wm * 64 + mt * 16 + g;
#pragma unroll
        for (int nt = 0; nt < 4; nt++) {
            int c = col0 + wn * 32 + nt * 8 + tig * 2;
            if (OUT_HALF) {
                __half* C = (__half*)Cout;
                *(uint32_t*)(C + (size_t)r * N + c)       = packh2(acc[mt][nt][0], acc[mt][nt][1]);
                *(uint32_t*)(C + (size_t)(r + 8) * N + c) = packh2(acc[mt][nt][2], acc[mt][nt][3]);
            } else {
                float* C = (float*)Cout;
                *(float2*)(C + (size_t)r * N + c)       = make_float2(acc[mt][nt][0], acc[mt][nt][1]);
                *(float2*)(C + (size_t)(r + 8) * N + c) = make_float2(acc[mt][nt][2], acc[mt][nt][3]);
            }
        }
    }
}

// ============ fp16 flash attention: register P, ldmatrix, cp.async, LPT order ============
#define FQ  128
#define FKT 64
#define FHS 136
#define FQO 0
#define FKO(st) (128 * FHS + (st) * 64 * FHS)
#define FVO (128 * FHS + 2 * 64 * FHS)
#define FLASH_SMEM_H ((FVO + 64 * FHS) * 2)

__global__ void __launch_bounds__(256)
flash_h(const __half* __restrict__ QKVb, __half* __restrict__ Ob) {
    extern __shared__ __half hsm[];
    const uint32_t sbase = smem_u32(hsm);
    const int qt = gridDim.x - 1 - blockIdx.x;   // longest-first (LPT) scheduling
    const int h = blockIdx.y, b = blockIdx.z;
    const int kvh = h >> 2;
    const int tid = threadIdx.x, lane = tid & 31, w = tid >> 5;
    const int g = lane >> 2, tig = lane & 3;
    const int q0 = qt * FQ;
    const int ntile = 2 * qt + 2;

    const int a_row_l = lane & 15, a_col_l = (lane >> 4) * 8;
    const int b_n_l = ((lane >> 4) & 1) * 8 + (lane & 7);
    const int b_k_l = ((lane >> 3) & 1) * 8;
    const int v_row_l = ((lane >> 3) & 1) * 8 + (lane & 7);
    const int v_col_l = (lane >> 4) * 8;

    const __half* Kb = QKVb + 2048 + kvh * HD;        // k columns
    const __half* Vb = Kb + 512;                      // v columns

    auto issueK = [&](int kt, int st) {
        uint32_t buf = sbase + (uint32_t)FKO(st) * 2;
#pragma unroll
        for (int j = 0; j < 4; j++) {
            int s = tid + j * 256;
            int r = s >> 4, c8 = (s & 15) << 3;
            cpasync16(buf + (uint32_t)(r * FHS + c8) * 2,
                      Kb + (size_t)(b * T_SZ + kt * FKT + r) * QKV_STR + c8);
        }
        cpcommit();
    };
    auto issueV = [&](int kt) {
        uint32_t buf = sbase + (uint32_t)FVO * 2;
#pragma unroll
        for (int j = 0; j < 4; j++) {
            int s = tid + j * 256;
            int r = s >> 4, c8 = (s & 15) << 3;
            cpasync16(buf + (uint32_t)(r * FHS + c8) * 2,
                      Vb + (size_t)(b * T_SZ + kt * FKT + r) * QKV_STR + c8);
        }
        cpcommit();
    };

    issueK(0, 0);

#pragma unroll
    for (int j = 0; j < 8; j++) {
        int s = tid + j * 256;
        int r = s >> 4, c8 = (s & 15) << 3;
        *(uint4*)&hsm[FQO + r * FHS + c8] =
            *(const uint4*)&QKVb[((size_t)(b * T_SZ + q0 + r)) * QKV_STR + h * HD + c8];
    }

    float O[16][4];
#pragma unroll
    for (int nt = 0; nt < 16; nt++)
#pragma unroll
        for (int j = 0; j < 4; j++) O[nt][j] = 0.f;
    float m0 = -1e30f, m1 = -1e30f, l0 = 0.f, l1 = 0.f;
    const int row_g = q0 + w * 16 + g;

    for (int kt = 0; kt < ntile; kt++) {
        const int k0 = kt * FKT;
        const bool more = (kt + 1 < ntile);
        issueV(kt);
        if (more) issueK(kt + 1, (kt + 1) & 1);
        if (more) cpwait<2>(); else cpwait<1>();
        __syncthreads();

        const uint32_t qbuf = sbase + (uint32_t)FQO * 2;
        const uint32_t kbuf = sbase + (uint32_t)FKO(kt & 1) * 2;

        float sfr[8][4];
#pragma unroll
        for (int nt = 0; nt < 8; nt++)
#pragma unroll
            for (int j = 0; j < 4; j++) sfr[nt][j] = 0.f;
#pragma unroll
        for (int ks = 0; ks < 8; ks++) {
            uint32_t a[4];
            ldsm4(a, qbuf + (uint32_t)((w * 16 + a_row_l) * FHS + ks * 16 + a_col_l) * 2);
#pragma unroll
            for (int ntp = 0; ntp < 4; ntp++) {
                uint32_t bf[4];
                ldsm4(bf, kbuf + (uint32_t)((ntp * 16 + b_n_l) * FHS + ks * 16 + b_k_l) * 2);
                mma_f16(sfr[2 * ntp],     a, &bf[0]);
                mma_f16(sfr[2 * ntp + 1], a, &bf[2]);
            }
        }

        if (k0 + FKT - 1 > q0 + w * 16) {
#pragma unroll
            for (int nt = 0; nt < 8; nt++) {
                int c = k0 + nt * 8 + 2 * tig;
                if (c     > row_g)     sfr[nt][0] = -1e30f;
                if (c + 1 > row_g)     sfr[nt][1] = -1e30f;
                if (c     > row_g + 8) sfr[nt][2] = -1e30f;
                if (c + 1 > row_g + 8) sfr[nt][3] = -1e30f;
            }
        }

        float mx0 = -1e30f, mx1 = -1e30f;
#pragma unroll
        for (int nt = 0; nt < 8; nt++) {
            mx0 = fmaxf(mx0, fmaxf(sfr[nt][0], sfr[nt][1]));
            mx1 = fmaxf(mx1, fmaxf(sfr[nt][2], sfr[nt][3]));
        }
        mx0 = fmaxf(mx0, __shfl_xor_sync(0xffffffffu, mx0, 1));
        mx0 = fmaxf(mx0, __shfl_xor_sync(0xffffffffu, mx0, 2));
        mx1 = fmaxf(mx1, __shfl_xor_sync(0xffffffffu, mx1, 1));
        mx1 = fmaxf(mx1, __shfl_xor_sync(0xffffffffu, mx1, 2));
        float mn0 = fmaxf(m0, mx0), mn1 = fmaxf(m1, mx1);
        float al0 = ex2(m0 - mn0), al1 = ex2(m1 - mn1);
        m0 = mn0; m1 = mn1;

        float ps0 = 0.f, ps1 = 0.f;
        uint32_t pa[4][4];
#pragma unroll
        for (int nt = 0; nt < 8; nt++) {
            float p0 = ex2(sfr[nt][0] - mn0);
            float p1 = ex2(sfr[nt][1] - mn0);
            float p2 = ex2(sfr[nt][2] - mn1);
            float p3 = ex2(sfr[nt][3] - mn1);
            ps0 += p0 + p1;
            ps1 += p2 + p3;
            pa[nt >> 1][(nt & 1) * 2 + 0] = packh2(p0, p1);
            pa[nt >> 1][(nt & 1) * 2 + 1] = packh2(p2, p3);
        }
        ps0 += __shfl_xor_sync(0xffffffffu, ps0, 1);
        ps0 += __shfl_xor_sync(0xffffffffu, ps0, 2);
        ps1 += __shfl_xor_sync(0xffffffffu, ps1, 1);
        ps1 += __shfl_xor_sync(0xffffffffu, ps1, 2);
        l0 = l0 * al0 + ps0;
        l1 = l1 * al1 + ps1;
#pragma unroll
        for (int nt = 0; nt < 16; nt++) {
            O[nt][0] *= al0; O[nt][1] *= al0;
            O[nt][2] *= al1; O[nt][3] *= al1;
        }

        if (more) cpwait<1>(); else cpwait<0>();
        __syncthreads();

        const uint32_t vbuf = sbase + (uint32_t)FVO * 2;
#pragma unroll
        for (int ks = 0; ks < 4; ks++) {
#pragma unroll
            for (int ntp = 0; ntp < 8; ntp++) {
                uint32_t bf[4];
                ldsm4t(bf, vbuf + (uint32_t)((ks * 16 + v_row_l) * FHS + ntp * 16 + v_col_l) * 2);
                mma_f16(O[2 * ntp],     pa[ks], &bf[0]);
                mma_f16(O[2 * ntp + 1], pa[ks], &bf[2]);
            }
        }
        __syncthreads();
    }

    float inv0 = 1.f / l0, inv1 = 1.f / l1;
    size_t r0 = (size_t)(b * T_SZ + row_g) * HID + h * HD;
    size_t r1 = (size_t)(b * T_SZ + row_g + 8) * HID + h * HD;
#pragma unroll
    for (int nt = 0; nt < 16; nt++) {
        int c = nt * 8 + 2 * tig;
        *(uint32_t*)&Ob[r0 + c] = packh2(O[nt][0] * inv0, O[nt][1] * inv0);
        *(uint32_t*)&Ob[r1 + c] = packh2(O[nt][2] * inv1, O[nt][3] * inv1);
    }
}

// ---------------- launch ----------------
extern "C" void kernel_launch(void* const* d_in, const int* in_sizes, int n_in,
                              void* d_out, int out_size) {
    const float* x  = (const float*)d_in[0];
    const float* Wq = (const float*)d_in[2];
    const float* Wk = (const float*)d_in[3];
    const float* Wv = (const float*)d_in[4];
    const float* Wo = (const float*)d_in[5];
    float* out = (float*)d_out;

    __half *qkv, *attn, *xh, *wqkv_h, *wo_h;
    cudaGetSymbolAddress((void**)&qkv, g_qkv);
    cudaGetSymbolAddress((void**)&attn, g_attn);
    cudaGetSymbolAddress((void**)&xh, g_xh);
    cudaGetSymbolAddress((void**)&wqkv_h, g_wqkv_h);
    cudaGetSymbolAddress((void**)&wo_h, g_wo_h);

    const int M = B_SZ * T_SZ;  // 4096
    const float qscale = 0.08838834764831843f * 1.4426950408889634f;

    cudaFuncSetAttribute(gemm_h<true>,  cudaFuncAttributeMaxDynamicSharedMemorySize, GEMM_SMEM);
    cudaFuncSetAttribute(gemm_h<false>, cudaFuncAttributeMaxDynamicSharedMemorySize, GEMM_SMEM);
    cudaFuncSetAttribute(flash_h, cudaFuncAttributeMaxDynamicSharedMemorySize, FLASH_SMEM_H);

    // fp16 prepass (Wq/Wk/Wv into concatenated weight)
    const int XE = M * HID / 8, WQE = HID * HID / 8, WKE = 512 * HID / 8;
    conv_half<<<(XE + 255) / 256, 256>>>((const float4*)x, (uint4*)xh, XE);
    conv_half<<<(WQE + 255) / 256, 256>>>((const float4*)Wq, (uint4*)wqkv_h, WQE);
    conv_half<<<(WKE + 255) / 256, 256>>>((const float4*)Wk, (uint4*)(wqkv_h + (size_t)2048 * HID), WKE);
    conv_half<<<(WKE + 255) / 256, 256>>>((const float4*)Wv, (uint4*)(wqkv_h + (size_t)2560 * HID), WKE);
    conv_half<<<(WQE + 255) / 256, 256>>>((const float4*)Wo, (uint4*)wo_h, WQE);

    // fused QKV projection (one launch, 768 blocks)
    gemm_h<true><<<dim3(QKV_STR / 128, M / 128), 256, GEMM_SMEM>>>(xh, wqkv_h, qkv, QKV_STR, HID);

    // RoPE (q part: folds softmax*log2e; k part: plain)
    build_rope_table<<<(T_SZ * 64 + 255) / 256, 256>>>();
    rope_half<<<(M * NH * 64 + 255) / 256, 256>>>(qkv, NH, QKV_STR, qscale);
    rope_half<<<(M * NKV * 64 + 255) / 256, 256>>>(qkv + 2048, NKV, QKV_STR, 1.0f);

    // attention
    flash_h<<<dim3(T_SZ / FQ, NH, B_SZ), 256, FLASH_SMEM_H>>>(qkv, attn);

    // output projection (float out)
    gemm_h<false><<<dim3(HID / 128, M / 128), 256, GEMM_SMEM>>>(attn, wo_h, out, HID, HID);
}

// round 13
// speedup vs baseline: 1.0864x; 1.0864x over previous
#include <cuda_runtime.h>
#include <cuda_fp16.h>
#include <math.h>
#include <stdint.h>

#define B_SZ 2
#define T_SZ 2048
#define HID  2048
#define NH   16
#define NKV  4
#define HD   128
#define QKV_STR 3072     // fused q|k|v row: q 0-2047, k 2048-2559, v 2560-3071

// ---------------- scratch ----------------
__device__ __half g_qkv[(size_t)B_SZ * T_SZ * QKV_STR];
__device__ __half g_attn[(size_t)B_SZ * T_SZ * HID];
__device__ __half g_xh[(size_t)B_SZ * T_SZ * HID];
__device__ __half g_wqkv_h[(size_t)QKV_STR * HID];
__device__ __half g_wo_h[(size_t)HID * HID];
__device__ float g_cos[T_SZ * 64];
__device__ float g_sin[T_SZ * 64];

// ---------------- helpers ----------------
__device__ __forceinline__ void mma_f16(float* d, const uint32_t* a, const uint32_t* b) {
    asm volatile(
        "mma.sync.aligned.m16n8k16.row.col.f32.f16.f16.f32 "
        "{%0,%1,%2,%3}, {%4,%5,%6,%7}, {%8,%9}, {%0,%1,%2,%3};\n"
        : "+f"(d[0]), "+f"(d[1]), "+f"(d[2]), "+f"(d[3])
        : "r"(a[0]), "r"(a[1]), "r"(a[2]), "r"(a[3]), "r"(b[0]), "r"(b[1]));
}
__device__ __forceinline__ void ldsm4(uint32_t* r, uint32_t addr) {
    asm volatile("ldmatrix.sync.aligned.m8n8.x4.shared.b16 {%0,%1,%2,%3}, [%4];"
        : "=r"(r[0]), "=r"(r[1]), "=r"(r[2]), "=r"(r[3]) : "r"(addr));
}
__device__ __forceinline__ void ldsm4t(uint32_t* r, uint32_t addr) {
    asm volatile("ldmatrix.sync.aligned.m8n8.x4.trans.shared.b16 {%0,%1,%2,%3}, [%4];"
        : "=r"(r[0]), "=r"(r[1]), "=r"(r[2]), "=r"(r[3]) : "r"(addr));
}
__device__ __forceinline__ float ex2(float x) {
    float y; asm("ex2.approx.ftz.f32 %0, %1;" : "=f"(y) : "f"(x)); return y;
}
__device__ __forceinline__ uint32_t smem_u32(const void* p) {
    uint32_t a;
    asm("{ .reg .u64 t; cvta.to.shared.u64 t, %1; cvt.u32.u64 %0, t; }" : "=r"(a) : "l"(p));
    return a;
}
__device__ __forceinline__ void cpasync16(uint32_t dst, const void* src) {
    asm volatile("cp.async.cg.shared.global [%0], [%1], 16;" :: "r"(dst), "l"(src));
}
__device__ __forceinline__ void cpcommit() {
    asm volatile("cp.async.commit_group;" ::: "memory");
}
template <int N> __device__ __forceinline__ void cpwait() {
    asm volatile("cp.async.wait_group %0;" :: "n"(N) : "memory");
}
__device__ __forceinline__ uint32_t packh2(float a, float b) {
    __half2 h = __floats2half2_rn(a, b);
    return *(uint32_t*)&h;
}

// ---------------- fp32 -> fp16 conversion prepass ----------------
__global__ void conv_half(const float4* __restrict__ in, uint4* __restrict__ out, int n8) {
    int i = blockIdx.x * blockDim.x + threadIdx.x;
    if (i >= n8) return;
    float4 a = in[2 * i], b = in[2 * i + 1];
    uint4 o;
    o.x = packh2(a.x, a.y); o.y = packh2(a.z, a.w);
    o.z = packh2(b.x, b.y); o.w = packh2(b.z, b.w);
    out[i] = o;
}

// ---------------- RoPE ----------------
__global__ void build_rope_table() {
    int idx = blockIdx.x * blockDim.x + threadIdx.x;
    if (idx >= T_SZ * 64) return;
    int i = idx & 63;
    int t = idx >> 6;
    double inv_freq = pow(10000.0, -(double)i / 64.0);
    double ang = (double)t * inv_freq;
    g_cos[idx] = (float)cos(ang);
    g_sin[idx] = (float)sin(ang);
}

__global__ void rope_half(__half* __restrict__ buf, int nheads, int rowstr, float scale) {
    int idx = blockIdx.x * blockDim.x + threadIdx.x;
    int total = B_SZ * T_SZ * nheads * 64;
    if (idx >= total) return;
    int i  = idx & 63;
    int h  = (idx >> 6) % nheads;
    int bt = idx / (64 * nheads);
    int t  = bt & (T_SZ - 1);
    float c = g_cos[t * 64 + i];
    float s = g_sin[t * 64 + i];
    __half* p = buf + (size_t)bt * rowstr + h * HD + i;
    float x1 = __half2float(p[0]), x2 = __half2float(p[64]);
    p[0]  = __float2half_rn((x1 * c - x2 * s) * scale);
    p[64] = __float2half_rn((x2 * c + x1 * s) * scale);
}

// ============ fp16 mma GEMM: C[M,N] = A[M,K]*B[N,K]^T, 3-stage, 1 sync/chunk ============
#define HS 72
#define G_ATILE (128 * HS)
#define G_STAGE (2 * G_ATILE)
#define GEMM_SMEM (3 * G_STAGE * 2)

template <bool OUT_HALF>
__global__ void __launch_bounds__(256)
gemm_h(const __half* __restrict__ A, const __half* __restrict__ Bm,
       void* __restrict__ Cout, int N, int K) {
    extern __shared__ __half hsm[];
    const uint32_t sbase = smem_u32(hsm);
    const int tid  = threadIdx.x;
    const int lane = tid & 31, w = tid >> 5;
    const int wm = w & 1, wn = w >> 1;
    const int g = lane >> 2, tig = lane & 3;
    const int row0 = blockIdx.y * 128, col0 = blockIdx.x * 128;
    const int nchunk = K / 64;

    const int a_row_l = lane & 15, a_col_l = (lane >> 4) * 8;
    const int b_n_l = ((lane >> 4) & 1) * 8 + (lane & 7);
    const int b_k_l = ((lane >> 3) & 1) * 8;

    float acc[4][4][4];
#pragma unroll
    for (int mt = 0; mt < 4; mt++)
#pragma unroll
        for (int nt = 0; nt < 4; nt++)
#pragma unroll
            for (int j = 0; j < 4; j++) acc[mt][nt][j] = 0.f;

    auto issue = [&](int ci, int st) {
        uint32_t abuf = sbase + (uint32_t)(st * G_STAGE) * 2;
        uint32_t bbuf = abuf + G_ATILE * 2;
#pragma unroll
        for (int j = 0; j < 4; j++) {
            int s = tid + j * 256;
            int r = s >> 3, c8 = (s & 7) << 3;
            cpasync16(abuf + (uint32_t)(r * HS + c8) * 2, A + (size_t)(row0 + r) * K + ci * 64 + c8);
            cpasync16(bbuf + (uint32_t)(r * HS + c8) * 2, Bm + (size_t)(col0 + r) * K + ci * 64 + c8);
        }
        cpcommit();
    };

    issue(0, 0);
    if (nchunk > 1) issue(1, 1);

    for (int i = 0; i < nchunk; i++) {
        const int st = i % 3;
        // groups issued so far: 0..min(i+1, nchunk-1); need group i complete
        if (i + 1 < nchunk) cpwait<1>();
        else                cpwait<0>();
        __syncthreads();           // tile i visible; stage (i+2)%3 free (read at i-1)
        if (i + 2 < nchunk) issue(i + 2, (i + 2) % 3);

        uint32_t abuf = sbase + (uint32_t)(st * G_STAGE) * 2;
        uint32_t bbuf = abuf + G_ATILE * 2;
#pragma unroll
        for (int ks = 0; ks < 4; ks++) {
            uint32_t af[4][4];
#pragma unroll
            for (int mt = 0; mt < 4; mt++)
                ldsm4(af[mt], abuf + (uint32_t)((wm * 64 + mt * 16 + a_row_l) * HS + ks * 16 + a_col_l) * 2);
            uint32_t bf[2][4];
#pragma unroll
            for (int ntp = 0; ntp < 2; ntp++)
                ldsm4(bf[ntp], bbuf + (uint32_t)((wn * 32 + ntp * 16 + b_n_l) * HS + ks * 16 + b_k_l) * 2);
#pragma unroll
            for (int mt = 0; mt < 4; mt++)
#pragma unroll
                for (int nt = 0; nt < 4; nt++)
                    mma_f16(acc[mt][nt], af[mt], &bf[nt >> 1][(nt & 1) * 2]);
        }
    }

#pragma unroll
    for (int mt = 0; mt < 4; mt++) {
        int r = row0 + wm * 64 + mt * 16 + g;
#pragma unroll
        for (int nt = 0; nt < 4; nt++) {
            int c = col0 + wn * 32 + nt * 8 + tig * 2;
            if (OUT_HALF) {
                __half* C = (__half*)Cout;
                *(uint32_t*)(C + (size_t)r * N + c)       = packh2(acc[mt][nt][0], acc[mt][nt][1]);
                *(uint32_t*)(C + (size_t)(r + 8) * N + c) = packh2(acc[mt][nt][2], acc[mt][nt][3]);
            } else {
                float* C = (float*)Cout;
                *(float2*)(C + (size_t)r * N + c)       = make_float2(acc[mt][nt][0], acc[mt][nt][1]);
                *(float2*)(C + (size_t)(r + 8) * N + c) = make_float2(acc[mt][nt][2], acc[mt][nt][3]);
            }
        }
    }
}

// ============ fp16 flash attention: hoisted Q frags, K+V double-buffered, 1 sync/tile ============
#define FQ  128
#define FKT 64
#define FHS 136
#define FQO 0
#define FKO(st) (128 * FHS + (st) * 64 * FHS)
#define FVO(st) (128 * FHS + 2 * 64 * FHS + (st) * 64 * FHS)
#define FLASH_SMEM_H ((128 * FHS + 4 * 64 * FHS) * 2)

__global__ void __launch_bounds__(256)
flash_h(const __half* __restrict__ QKVb, __half* __restrict__ Ob) {
    extern __shared__ __half hsm[];
    const uint32_t sbase = smem_u32(hsm);
    const int qt = gridDim.x - 1 - blockIdx.x;   // longest-first
    const int h = blockIdx.y, b = blockIdx.z;
    const int kvh = h >> 2;
    const int tid = threadIdx.x, lane = tid & 31, w = tid >> 5;
    const int g = lane >> 2, tig = lane & 3;
    const int q0 = qt * FQ;
    const int ntile = 2 * qt + 2;

    const int a_row_l = lane & 15, a_col_l = (lane >> 4) * 8;
    const int b_n_l = ((lane >> 4) & 1) * 8 + (lane & 7);
    const int b_k_l = ((lane >> 3) & 1) * 8;
    const int v_row_l = ((lane >> 3) & 1) * 8 + (lane & 7);
    const int v_col_l = (lane >> 4) * 8;

    const __half* Kb = QKVb + 2048 + kvh * HD;
    const __half* Vb = Kb + 512;

    // one commit group per kv tile: K + V together
    auto issueKV = [&](int kt, int st) {
        uint32_t kb = sbase + (uint32_t)FKO(st) * 2;
        uint32_t vb = sbase + (uint32_t)FVO(st) * 2;
#pragma unroll
        for (int j = 0; j < 4; j++) {
            int s = tid + j * 256;
            int r = s >> 4, c8 = (s & 15) << 3;
            size_t row = (size_t)(b * T_SZ + kt * FKT + r) * QKV_STR;
            cpasync16(kb + (uint32_t)(r * FHS + c8) * 2, Kb + row + c8);
            cpasync16(vb + (uint32_t)(r * FHS + c8) * 2, Vb + row + c8);
        }
        cpcommit();
    };

    issueKV(0, 0);

    // Q tile -> smem -> hoisted A-fragments (loop-invariant)
#pragma unroll
    for (int j = 0; j < 8; j++) {
        int s = tid + j * 256;
        int r = s >> 4, c8 = (s & 15) << 3;
        *(uint4*)&hsm[FQO + r * FHS + c8] =
            *(const uint4*)&QKVb[((size_t)(b * T_SZ + q0 + r)) * QKV_STR + h * HD + c8];
    }
    __syncthreads();
    uint32_t qa[8][4];
#pragma unroll
    for (int ks = 0; ks < 8; ks++)
        ldsm4(qa[ks], sbase + (uint32_t)((FQO + (w * 16 + a_row_l) * FHS + ks * 16 + a_col_l)) * 2);

    float O[16][4];
#pragma unroll
    for (int nt = 0; nt < 16; nt++)
#pragma unroll
        for (int j = 0; j < 4; j++) O[nt][j] = 0.f;
    float m0 = -1e30f, m1 = -1e30f, l0 = 0.f, l1 = 0.f;
    const int row_g = q0 + w * 16 + g;

    for (int kt = 0; kt < ntile; kt++) {
        const int k0 = kt * FKT;
        const int st = kt & 1;
        cpwait<0>();               // group kt complete (issued last iter / prologue)
        __syncthreads();           // tile visible; stage (kt+1)&1 free (read at kt-1)
        if (kt + 1 < ntile) issueKV(kt + 1, (kt + 1) & 1);

        const uint32_t kbuf = sbase + (uint32_t)FKO(st) * 2;
        float sfr[8][4];
#pragma unroll
        for (int nt = 0; nt < 8; nt++)
#pragma unroll
            for (int j = 0; j < 4; j++) sfr[nt][j] = 0.f;
#pragma unroll
        for (int ks = 0; ks < 8; ks++) {
#pragma unroll
            for (int ntp = 0; ntp < 4; ntp++) {
                uint32_t bf[4];
                ldsm4(bf, kbuf + (uint32_t)((ntp * 16 + b_n_l) * FHS + ks * 16 + b_k_l) * 2);
                mma_f16(sfr[2 * ntp],     qa[ks], &bf[0]);
                mma_f16(sfr[2 * ntp + 1], qa[ks], &bf[2]);
            }
        }

        if (k0 + FKT - 1 > q0 + w * 16) {
#pragma unroll
            for (int nt = 0; nt < 8; nt++) {
                int c = k0 + nt * 8 + 2 * tig;
                if (c     > row_g)     sfr[nt][0] = -1e30f;
                if (c + 1 > row_g)     sfr[nt][1] = -1e30f;
                if (c     > row_g + 8) sfr[nt][2] = -1e30f;
                if (c + 1 > row_g + 8) sfr[nt][3] = -1e30f;
            }
        }

        float mx0 = -1e30f, mx1 = -1e30f;
#pragma unroll
        for (int nt = 0; nt < 8; nt++) {
            mx0 = fmaxf(mx0, fmaxf(sfr[nt][0], sfr[nt][1]));
            mx1 = fmaxf(mx1, fmaxf(sfr[nt][2], sfr[nt][3]));
        }
        mx0 = fmaxf(mx0, __shfl_xor_sync(0xffffffffu, mx0, 1));
        mx0 = fmaxf(mx0, __shfl_xor_sync(0xffffffffu, mx0, 2));
        mx1 = fmaxf(mx1, __shfl_xor_sync(0xffffffffu, mx1, 1));
        mx1 = fmaxf(mx1, __shfl_xor_sync(0xffffffffu, mx1, 2));
        float mn0 = fmaxf(m0, mx0), mn1 = fmaxf(m1, mx1);
        float al0 = ex2(m0 - mn0), al1 = ex2(m1 - mn1);
        m0 = mn0; m1 = mn1;

        float ps0 = 0.f, ps1 = 0.f;
        uint32_t pa[4][4];
#pragma unroll
        for (int nt = 0; nt < 8; nt++) {
            float p0 = ex2(sfr[nt][0] - mn0);
            float p1 = ex2(sfr[nt][1] - mn0);
            float p2 = ex2(sfr[nt][2] - mn1);
            float p3 = ex2(sfr[nt][3] - mn1);
            ps0 += p0 + p1;
            ps1 += p2 + p3;
            pa[nt >> 1][(nt & 1) * 2 + 0] = packh2(p0, p1);
            pa[nt >> 1][(nt & 1) * 2 + 1] = packh2(p2, p3);
        }
        ps0 += __shfl_xor_sync(0xffffffffu, ps0, 1);
        ps0 += __shfl_xor_sync(0xffffffffu, ps0, 2);
        ps1 += __shfl_xor_sync(0xffffffffu, ps1, 1);
        ps1 += __shfl_xor_sync(0xffffffffu, ps1, 2);
        l0 = l0 * al0 + ps0;
        l1 = l1 * al1 + ps1;
#pragma unroll
        for (int nt = 0; nt < 16; nt++) {
            O[nt][0] *= al0; O[nt][1] *= al0;
            O[nt][2] *= al1; O[nt][3] *= al1;
        }

        const uint32_t vbuf = sbase + (uint32_t)FVO(st) * 2;
#pragma unroll
        for (int ks = 0; ks < 4; ks++) {
#pragma unroll
            for (int ntp = 0; ntp < 8; ntp++) {
                uint32_t bf[4];
                ldsm4t(bf, vbuf + (uint32_t)((ks * 16 + v_row_l) * FHS + ntp * 16 + v_col_l) * 2);
                mma_f16(O[2 * ntp],     pa[ks], &bf[0]);
                mma_f16(O[2 * ntp + 1], pa[ks], &bf[2]);
            }
        }
        // no trailing sync: next iter's barrier (after cpwait) frees this stage
    }

    float inv0 = 1.f / l0, inv1 = 1.f / l1;
    size_t r0 = (size_t)(b * T_SZ + row_g) * HID + h * HD;
    size_t r1 = (size_t)(b * T_SZ + row_g + 8) * HID + h * HD;
#pragma unroll
    for (int nt = 0; nt < 16; nt++) {
        int c = nt * 8 + 2 * tig;
        *(uint32_t*)&Ob[r0 + c] = packh2(O[nt][0] * inv0, O[nt][1] * inv0);
        *(uint32_t*)&Ob[r1 + c] = packh2(O[nt][2] * inv1, O[nt][3] * inv1);
    }
}

// ---------------- launch ----------------
extern "C" void kernel_launch(void* const* d_in, const int* in_sizes, int n_in,
                              void* d_out, int out_size) {
    const float* x  = (const float*)d_in[0];
    const float* Wq = (const float*)d_in[2];
    const float* Wk = (const float*)d_in[3];
    const float* Wv = (const float*)d_in[4];
    const float* Wo = (const float*)d_in[5];
    float* out = (float*)d_out;

    __half *qkv, *attn, *xh, *wqkv_h, *wo_h;
    cudaGetSymbolAddress((void**)&qkv, g_qkv);
    cudaGetSymbolAddress((void**)&attn, g_attn);
    cudaGetSymbolAddress((void**)&xh, g_xh);
    cudaGetSymbolAddress((void**)&wqkv_h, g_wqkv_h);
    cudaGetSymbolAddress((void**)&wo_h, g_wo_h);

    const int M = B_SZ * T_SZ;  // 4096
    const float qscale = 0.08838834764831843f * 1.4426950408889634f;

    cudaFuncSetAttribute(gemm_h<true>,  cudaFuncAttributeMaxDynamicSharedMemorySize, GEMM_SMEM);
    cudaFuncSetAttribute(gemm_h<false>, cudaFuncAttributeMaxDynamicSharedMemorySize, GEMM_SMEM);
    cudaFuncSetAttribute(flash_h, cudaFuncAttributeMaxDynamicSharedMemorySize, FLASH_SMEM_H);

    // fp16 prepass
    const int XE = M * HID / 8, WQE = HID * HID / 8, WKE = 512 * HID / 8;
    conv_half<<<(XE + 255) / 256, 256>>>((const float4*)x, (uint4*)xh, XE);
    conv_half<<<(WQE + 255) / 256, 256>>>((const float4*)Wq, (uint4*)wqkv_h, WQE);
    conv_half<<<(WKE + 255) / 256, 256>>>((const float4*)Wk, (uint4*)(wqkv_h + (size_t)2048 * HID), WKE);
    conv_half<<<(WKE + 255) / 256, 256>>>((const float4*)Wv, (uint4*)(wqkv_h + (size_t)2560 * HID), WKE);
    conv_half<<<(WQE + 255) / 256, 256>>>((const float4*)Wo, (uint4*)wo_h, WQE);

    // fused QKV projection
    gemm_h<true><<<dim3(QKV_STR / 128, M / 128), 256, GEMM_SMEM>>>(xh, wqkv_h, qkv, QKV_STR, HID);

    // RoPE
    build_rope_table<<<(T_SZ * 64 + 255) / 256, 256>>>();
    rope_half<<<(M * NH * 64 + 255) / 256, 256>>>(qkv, NH, QKV_STR, qscale);
    rope_half<<<(M * NKV * 64 + 255) / 256, 256>>>(qkv + 2048, NKV, QKV_STR, 1.0f);

    // attention
    flash_h<<<dim3(T_SZ / FQ, NH, B_SZ), 256, FLASH_SMEM_H>>>(qkv, attn);

    // output projection (float out)
    gemm_h<false><<<dim3(HID / 128, M / 128), 256, GEMM_SMEM>>>(attn, wo_h, out, HID, HID);
}

// round 15
// speedup vs baseline: 1.1281x; 1.0384x over previous
#include <cuda_runtime.h>
#include <cuda_fp16.h>
#include <math.h>
#include <stdint.h>

#define B_SZ 2
#define T_SZ 2048
#define HID  2048
#define NH   16
#define NKV  4
#define HD   128
#define QKV_STR 3072     // fused q|k|v row: q 0-2047, k 2048-2559, v 2560-3071

// ---------------- scratch ----------------
__device__ __half g_qkv[(size_t)B_SZ * T_SZ * QKV_STR];
__device__ __half g_attn[(size_t)B_SZ * T_SZ * HID];
__device__ __half g_xh[(size_t)B_SZ * T_SZ * HID];
__device__ __half g_wqkv_h[(size_t)QKV_STR * HID];
__device__ __half g_wo_h[(size_t)HID * HID];
__device__ float g_cos[T_SZ * 64];
__device__ float g_sin[T_SZ * 64];

// ---------------- helpers ----------------
__device__ __forceinline__ void mma_f16(float* d, const uint32_t* a, const uint32_t* b) {
    asm volatile(
        "mma.sync.aligned.m16n8k16.row.col.f32.f16.f16.f32 "
        "{%0,%1,%2,%3}, {%4,%5,%6,%7}, {%8,%9}, {%0,%1,%2,%3};\n"
        : "+f"(d[0]), "+f"(d[1]), "+f"(d[2]), "+f"(d[3])
        : "r"(a[0]), "r"(a[1]), "r"(a[2]), "r"(a[3]), "r"(b[0]), "r"(b[1]));
}
__device__ __forceinline__ void ldsm4(uint32_t* r, uint32_t addr) {
    asm volatile("ldmatrix.sync.aligned.m8n8.x4.shared.b16 {%0,%1,%2,%3}, [%4];"
        : "=r"(r[0]), "=r"(r[1]), "=r"(r[2]), "=r"(r[3]) : "r"(addr));
}
__device__ __forceinline__ void ldsm4t(uint32_t* r, uint32_t addr) {
    asm volatile("ldmatrix.sync.aligned.m8n8.x4.trans.shared.b16 {%0,%1,%2,%3}, [%4];"
        : "=r"(r[0]), "=r"(r[1]), "=r"(r[2]), "=r"(r[3]) : "r"(addr));
}
__device__ __forceinline__ float ex2(float x) {
    float y; asm("ex2.approx.ftz.f32 %0, %1;" : "=f"(y) : "f"(x)); return y;
}
__device__ __forceinline__ uint32_t smem_u32(const void* p) {
    uint32_t a;
    asm("{ .reg .u64 t; cvta.to.shared.u64 t, %1; cvt.u32.u64 %0, t; }" : "=r"(a) : "l"(p));
    return a;
}
__device__ __forceinline__ void cpasync16(uint32_t dst, const void* src) {
    asm volatile("cp.async.cg.shared.global [%0], [%1], 16;" :: "r"(dst), "l"(src));
}
__device__ __forceinline__ void cpcommit() {
    asm volatile("cp.async.commit_group;" ::: "memory");
}
template <int N> __device__ __forceinline__ void cpwait() {
    asm volatile("cp.async.wait_group %0;" :: "n"(N) : "memory");
}
__device__ __forceinline__ uint32_t packh2(float a, float b) {
    __half2 h = __floats2half2_rn(a, b);
    return *(uint32_t*)&h;
}

// ---------------- fp32 -> fp16 conversion prepass ----------------
__global__ void conv_half(const float4* __restrict__ in, uint4* __restrict__ out, int n8) {
    int i = blockIdx.x * blockDim.x + threadIdx.x;
    if (i >= n8) return;
    float4 a = in[2 * i], b = in[2 * i + 1];
    uint4 o;
    o.x = packh2(a.x, a.y); o.y = packh2(a.z, a.w);
    o.z = packh2(b.x, b.y); o.w = packh2(b.z, b.w);
    out[i] = o;
}

// ---------------- RoPE ----------------
__global__ void build_rope_table() {
    int idx = blockIdx.x * blockDim.x + threadIdx.x;
    if (idx >= T_SZ * 64) return;
    int i = idx & 63;
    int t = idx >> 6;
    double inv_freq = pow(10000.0, -(double)i / 64.0);
    double ang = (double)t * inv_freq;
    g_cos[idx] = (float)cos(ang);
    g_sin[idx] = (float)sin(ang);
}

__global__ void rope_half(__half* __restrict__ buf, int nheads, int rowstr, float scale) {
    int idx = blockIdx.x * blockDim.x + threadIdx.x;
    int total = B_SZ * T_SZ * nheads * 64;
    if (idx >= total) return;
    int i  = idx & 63;
    int h  = (idx >> 6) % nheads;
    int bt = idx / (64 * nheads);
    int t  = bt & (T_SZ - 1);
    float c = g_cos[t * 64 + i];
    float s = g_sin[t * 64 + i];
    __half* p = buf + (size_t)bt * rowstr + h * HD + i;
    float x1 = __half2float(p[0]), x2 = __half2float(p[64]);
    p[0]  = __float2half_rn((x1 * c - x2 * s) * scale);
    p[64] = __float2half_rn((x2 * c + x1 * s) * scale);
}

// ============ fp16 mma GEMM: swizzled smem (no pad), 3-stage, 1 sync/chunk, 2 CTA/SM ============
// Tile 128x128, BK=64 halves. Row = 64 halves (128B). Swizzle: 16B-chunk idx ^= row&7.
#define G_TILE_H (128 * 64)
#define G_STAGE_H (2 * G_TILE_H)
#define GEMM_SMEM (3 * G_STAGE_H * 2)       // 98304 bytes

__device__ __forceinline__ uint32_t gswz(int row, int chunk) {   // halves offset
    return (uint32_t)(row * 64 + 8 * (chunk ^ (row & 7)));
}

template <bool OUT_HALF>
__global__ void __launch_bounds__(256, 2)
gemm_h(const __half* __restrict__ A, const __half* __restrict__ Bm,
       void* __restrict__ Cout, int N, int K) {
    extern __shared__ __half hsm[];
    const uint32_t sbase = smem_u32(hsm);
    const int tid  = threadIdx.x;
    const int lane = tid & 31, w = tid >> 5;
    const int wm = w & 1, wn = w >> 1;
    const int g = lane >> 2, tig = lane & 3;
    const int row0 = blockIdx.y * 128, col0 = blockIdx.x * 128;
    const int nchunk = K / 64;

    const int a_row_l = lane & 15, a_ch_l = lane >> 4;
    const int b_n_l = ((lane >> 4) & 1) * 8 + (lane & 7);
    const int b_ch_l = (lane >> 3) & 1;

    float acc[4][4][4];
#pragma unroll
    for (int mt = 0; mt < 4; mt++)
#pragma unroll
        for (int nt = 0; nt < 4; nt++)
#pragma unroll
            for (int j = 0; j < 4; j++) acc[mt][nt][j] = 0.f;

    auto issue = [&](int ci, int st) {
        uint32_t abuf = sbase + (uint32_t)(st * G_STAGE_H) * 2;
        uint32_t bbuf = abuf + G_TILE_H * 2;
#pragma unroll
        for (int j = 0; j < 4; j++) {
            int s = tid + j * 256;
            int r = s >> 3, c = s & 7;                 // 128 rows x 8 chunks
            cpasync16(abuf + gswz(r, c) * 2, A + (size_t)(row0 + r) * K + ci * 64 + c * 8);
            cpasync16(bbuf + gswz(r, c) * 2, Bm + (size_t)(col0 + r) * K + ci * 64 + c * 8);
        }
        cpcommit();
    };

    issue(0, 0);
    if (nchunk > 1) issue(1, 1);

    for (int i = 0; i < nchunk; i++) {
        const int st = i % 3;
        if (i + 1 < nchunk) cpwait<1>();
        else                cpwait<0>();
        __syncthreads();
        if (i + 2 < nchunk) issue(i + 2, (i + 2) % 3);

        uint32_t abuf = sbase + (uint32_t)(st * G_STAGE_H) * 2;
        uint32_t bbuf = abuf + G_TILE_H * 2;
#pragma unroll
        for (int ks = 0; ks < 4; ks++) {
            uint32_t af[4][4];
#pragma unroll
            for (int mt = 0; mt < 4; mt++)
                ldsm4(af[mt], abuf + gswz(wm * 64 + mt * 16 + a_row_l, ks * 2 + a_ch_l) * 2);
            uint32_t bf[2][4];
#pragma unroll
            for (int ntp = 0; ntp < 2; ntp++)
                ldsm4(bf[ntp], bbuf + gswz(wn * 32 + ntp * 16 + b_n_l, ks * 2 + b_ch_l) * 2);
#pragma unroll
            for (int mt = 0; mt < 4; mt++)
#pragma unroll
                for (int nt = 0; nt < 4; nt++)
                    mma_f16(acc[mt][nt], af[mt], &bf[nt >> 1][(nt & 1) * 2]);
        }
    }

#pragma unroll
    for (int mt = 0; mt < 4; mt++) {
        int r = row0 + wm * 64 + mt * 16 + g;
#pragma unroll
        for (int nt = 0; nt < 4; nt++) {
            int c = col0 + wn * 32 + nt * 8 + tig * 2;
            if (OUT_HALF) {
                __half* C = (__half*)Cout;
                *(uint32_t*)(C + (size_t)r * N + c)       = packh2(acc[mt][nt][0], acc[mt][nt][1]);
                *(uint32_t*)(C + (size_t)(r + 8) * N + c) = packh2(acc[mt][nt][2], acc[mt][nt][3]);
            } else {
                float* C = (float*)Cout;
                *(float2*)(C + (size_t)r * N + c)       = make_float2(acc[mt][nt][0], acc[mt][nt][1]);
                *(float2*)(C + (size_t)(r + 8) * N + c) = make_float2(acc[mt][nt][2], acc[mt][nt][3]);
            }
        }
    }
}

// ============ fp16 flash attention: 64-row q tiles, 128 threads, 2 CTA/SM ============
#define FQ  64
#define FKT 64
#define FHS 136
#define FQO 0
#define FKO(st) (FQ * FHS + (st) * 64 * FHS)
#define FVO(st) (FQ * FHS + 2 * 64 * FHS + (st) * 64 * FHS)
#define FLASH_SMEM_H ((FQ * FHS + 4 * 64 * FHS) * 2)   // 87040 bytes

__global__ void __launch_bounds__(128)
flash_h(const __half* __restrict__ QKVb, __half* __restrict__ Ob) {
    extern __shared__ __half hsm[];
    const uint32_t sbase = smem_u32(hsm);
    const int qt = gridDim.x - 1 - blockIdx.x;   // longest-first
    const int h = blockIdx.y, b = blockIdx.z;
    const int kvh = h >> 2;
    const int tid = threadIdx.x, lane = tid & 31, w = tid >> 5;   // 4 warps
    const int g = lane >> 2, tig = lane & 3;
    const int q0 = qt * FQ;
    const int ntile = qt + 1;

    const int a_row_l = lane & 15, a_col_l = (lane >> 4) * 8;
    const int b_n_l = ((lane >> 4) & 1) * 8 + (lane & 7);
    const int b_k_l = ((lane >> 3) & 1) * 8;
    const int v_row_l = ((lane >> 3) & 1) * 8 + (lane & 7);
    const int v_col_l = (lane >> 4) * 8;

    const __half* Kb = QKVb + 2048 + kvh * HD;
    const __half* Vb = Kb + 512;

    // FIX (round-14 NaN): 128 threads x 8 iters = 1024 slots = 64 rows x 16 chunks.
    auto issueKV = [&](int kt, int st) {
        uint32_t kb = sbase + (uint32_t)FKO(st) * 2;
        uint32_t vb = sbase + (uint32_t)FVO(st) * 2;
#pragma unroll
        for (int j = 0; j < 8; j++) {
            int s = tid + j * 128;
            int r = s >> 4, c8 = (s & 15) << 3;
            size_t row = (size_t)(b * T_SZ + kt * FKT + r) * QKV_STR;
            cpasync16(kb + (uint32_t)(r * FHS + c8) * 2, Kb + row + c8);
            cpasync16(vb + (uint32_t)(r * FHS + c8) * 2, Vb + row + c8);
        }
        cpcommit();
    };

    issueKV(0, 0);

    // Q tile -> smem -> hoisted A-fragments
#pragma unroll
    for (int j = 0; j < 8; j++) {
        int s = tid + j * 128;
        int r = s >> 4, c8 = (s & 15) << 3;
        *(uint4*)&hsm[FQO + r * FHS + c8] =
            *(const uint4*)&QKVb[((size_t)(b * T_SZ + q0 + r)) * QKV_STR + h * HD + c8];
    }
    __syncthreads();
    uint32_t qa[8][4];
#pragma unroll
    for (int ks = 0; ks < 8; ks++)
        ldsm4(qa[ks], sbase + (uint32_t)((FQO + (w * 16 + a_row_l) * FHS + ks * 16 + a_col_l)) * 2);

    float O[16][4];
#pragma unroll
    for (int nt = 0; nt < 16; nt++)
#pragma unroll
        for (int j = 0; j < 4; j++) O[nt][j] = 0.f;
    float m0 = -1e30f, m1 = -1e30f, l0 = 0.f, l1 = 0.f;
    const int row_g = q0 + w * 16 + g;

    for (int kt = 0; kt < ntile; kt++) {
        const int k0 = kt * FKT;
        const int st = kt & 1;
        cpwait<0>();
        __syncthreads();
        if (kt + 1 < ntile) issueKV(kt + 1, (kt + 1) & 1);

        const uint32_t kbuf = sbase + (uint32_t)FKO(st) * 2;
        float sfr[8][4];
#pragma unroll
        for (int nt = 0; nt < 8; nt++)
#pragma unroll
            for (int j = 0; j < 4; j++) sfr[nt][j] = 0.f;
#pragma unroll
        for (int ks = 0; ks < 8; ks++) {
#pragma unroll
            for (int ntp = 0; ntp < 4; ntp++) {
                uint32_t bf[4];
                ldsm4(bf, kbuf + (uint32_t)((ntp * 16 + b_n_l) * FHS + ks * 16 + b_k_l) * 2);
                mma_f16(sfr[2 * ntp],     qa[ks], &bf[0]);
                mma_f16(sfr[2 * ntp + 1], qa[ks], &bf[2]);
            }
        }

        if (k0 + FKT - 1 > q0 + w * 16) {
#pragma unroll
            for (int nt = 0; nt < 8; nt++) {
                int c = k0 + nt * 8 + 2 * tig;
                if (c     > row_g)     sfr[nt][0] = -1e30f;
                if (c + 1 > row_g)     sfr[nt][1] = -1e30f;
                if (c     > row_g + 8) sfr[nt][2] = -1e30f;
                if (c + 1 > row_g + 8) sfr[nt][3] = -1e30f;
            }
        }

        float mx0 = -1e30f, mx1 = -1e30f;
#pragma unroll
        for (int nt = 0; nt < 8; nt++) {
            mx0 = fmaxf(mx0, fmaxf(sfr[nt][0], sfr[nt][1]));
            mx1 = fmaxf(mx1, fmaxf(sfr[nt][2], sfr[nt][3]));
        }
        mx0 = fmaxf(mx0, __shfl_xor_sync(0xffffffffu, mx0, 1));
        mx0 = fmaxf(mx0, __shfl_xor_sync(0xffffffffu, mx0, 2));
        mx1 = fmaxf(mx1, __shfl_xor_sync(0xffffffffu, mx1, 1));
        mx1 = fmaxf(mx1, __shfl_xor_sync(0xffffffffu, mx1, 2));
        float mn0 = fmaxf(m0, mx0), mn1 = fmaxf(m1, mx1);
        float al0 = ex2(m0 - mn0), al1 = ex2(m1 - mn1);
        m0 = mn0; m1 = mn1;

        float ps0 = 0.f, ps1 = 0.f;
        uint32_t pa[4][4];
#pragma unroll
        for (int nt = 0; nt < 8; nt++) {
            float p0 = ex2(sfr[nt][0] - mn0);
            float p1 = ex2(sfr[nt][1] - mn0);
            float p2 = ex2(sfr[nt][2] - mn1);
            float p3 = ex2(sfr[nt][3] - mn1);
            ps0 += p0 + p1;
            ps1 += p2 + p3;
            pa[nt >> 1][(nt & 1) * 2 + 0] = packh2(p0, p1);
            pa[nt >> 1][(nt & 1) * 2 + 1] = packh2(p2, p3);
        }
        ps0 += __shfl_xor_sync(0xffffffffu, ps0, 1);
        ps0 += __shfl_xor_sync(0xffffffffu, ps0, 2);
        ps1 += __shfl_xor_sync(0xffffffffu, ps1, 1);
        ps1 += __shfl_xor_sync(0xffffffffu, ps1, 2);
        l0 = l0 * al0 + ps0;
        l1 = l1 * al1 + ps1;
#pragma unroll
        for (int nt = 0; nt < 16; nt++) {
            O[nt][0] *= al0; O[nt][1] *= al0;
            O[nt][2] *= al1; O[nt][3] *= al1;
        }

        const uint32_t vbuf = sbase + (uint32_t)FVO(st) * 2;
#pragma unroll
        for (int ks = 0; ks < 4; ks++) {
#pragma unroll
            for (int ntp = 0; ntp < 8; ntp++) {
                uint32_t bf[4];
                ldsm4t(bf, vbuf + (uint32_t)((ks * 16 + v_row_l) * FHS + ntp * 16 + v_col_l) * 2);
                mma_f16(O[2 * ntp],     pa[ks], &bf[0]);
                mma_f16(O[2 * ntp + 1], pa[ks], &bf[2]);
            }
        }
        // next iteration's barrier (after cpwait) frees this stage
    }

    float inv0 = 1.f / l0, inv1 = 1.f / l1;
    size_t r0 = (size_t)(b * T_SZ + row_g) * HID + h * HD;
    size_t r1 = (size_t)(b * T_SZ + row_g + 8) * HID + h * HD;
#pragma unroll
    for (int nt = 0; nt < 16; nt++) {
        int c = nt * 8 + 2 * tig;
        *(uint32_t*)&Ob[r0 + c] = packh2(O[nt][0] * inv0, O[nt][1] * inv0);
        *(uint32_t*)&Ob[r1 + c] = packh2(O[nt][2] * inv1, O[nt][3] * inv1);
    }
}

// ---------------- launch ----------------
extern "C" void kernel_launch(void* const* d_in, const int* in_sizes, int n_in,
                              void* d_out, int out_size) {
    const float* x  = (const float*)d_in[0];
    const float* Wq = (const float*)d_in[2];
    const float* Wk = (const float*)d_in[3];
    const float* Wv = (const float*)d_in[4];
    const float* Wo = (const float*)d_in[5];
    float* out = (float*)d_out;

    __half *qkv, *attn, *xh, *wqkv_h, *wo_h;
    cudaGetSymbolAddress((void**)&qkv, g_qkv);
    cudaGetSymbolAddress((void**)&attn, g_attn);
    cudaGetSymbolAddress((void**)&xh, g_xh);
    cudaGetSymbolAddress((void**)&wqkv_h, g_wqkv_h);
    cudaGetSymbolAddress((void**)&wo_h, g_wo_h);

    const int M = B_SZ * T_SZ;  // 4096
    const float qscale = 0.08838834764831843f * 1.4426950408889634f;

    cudaFuncSetAttribute(gemm_h<true>,  cudaFuncAttributeMaxDynamicSharedMemorySize, GEMM_SMEM);
    cudaFuncSetAttribute(gemm_h<false>, cudaFuncAttributeMaxDynamicSharedMemorySize, GEMM_SMEM);
    cudaFuncSetAttribute(flash_h, cudaFuncAttributeMaxDynamicSharedMemorySize, FLASH_SMEM_H);

    // fp16 prepass
    const int XE = M * HID / 8, WQE = HID * HID / 8, WKE = 512 * HID / 8;
    conv_half<<<(XE + 255) / 256, 256>>>((const float4*)x, (uint4*)xh, XE);
    conv_half<<<(WQE + 255) / 256, 256>>>((const float4*)Wq, (uint4*)wqkv_h, WQE);
    conv_half<<<(WKE + 255) / 256, 256>>>((const float4*)Wk, (uint4*)(wqkv_h + (size_t)2048 * HID), WKE);
    conv_half<<<(WKE + 255) / 256, 256>>>((const float4*)Wv, (uint4*)(wqkv_h + (size_t)2560 * HID), WKE);
    conv_half<<<(WQE + 255) / 256, 256>>>((const float4*)Wo, (uint4*)wo_h, WQE);

    // fused QKV projection
    gemm_h<true><<<dim3(QKV_STR / 128, M / 128), 256, GEMM_SMEM>>>(xh, wqkv_h, qkv, QKV_STR, HID);

    // RoPE
    build_rope_table<<<(T_SZ * 64 + 255) / 256, 256>>>();
    rope_half<<<(M * NH * 64 + 255) / 256, 256>>>(qkv, NH, QKV_STR, qscale);
    rope_half<<<(M * NKV * 64 + 255) / 256, 256>>>(qkv + 2048, NKV, QKV_STR, 1.0f);

    // attention (64-row tiles, 2 CTA/SM)
    flash_h<<<dim3(T_SZ / FQ, NH, B_SZ), 128, FLASH_SMEM_H>>>(qkv, attn);

    // output projection (float out)
    gemm_h<false><<<dim3(HID / 128, M / 128), 256, GEMM_SMEM>>>(attn, wo_h, out, HID, HID);
}

// round 16
// speedup vs baseline: 1.1819x; 1.0477x over previous
#include <cuda_runtime.h>
#include <cuda_fp16.h>
#include <math.h>
#include <stdint.h>

#define B_SZ 2
#define T_SZ 2048
#define HID  2048
#define NH   16
#define NKV  4
#define HD   128
#define QKV_STR 3072     // fused q|k|v row: q 0-2047, k 2048-2559, v 2560-3071

// ---------------- scratch ----------------
__device__ __half g_qkv[(size_t)B_SZ * T_SZ * QKV_STR];
__device__ __half g_attn[(size_t)B_SZ * T_SZ * HID];
__device__ __half g_xh[(size_t)B_SZ * T_SZ * HID];
__device__ __half g_wqkv_h[(size_t)QKV_STR * HID];
__device__ __half g_wo_h[(size_t)HID * HID];
__device__ float g_cos[T_SZ * 64];
__device__ float g_sin[T_SZ * 64];

// ---------------- helpers ----------------
__device__ __forceinline__ void mma_f16(float* d, const uint32_t* a, const uint32_t* b) {
    asm volatile(
        "mma.sync.aligned.m16n8k16.row.col.f32.f16.f16.f32 "
        "{%0,%1,%2,%3}, {%4,%5,%6,%7}, {%8,%9}, {%0,%1,%2,%3};\n"
        : "+f"(d[0]), "+f"(d[1]), "+f"(d[2]), "+f"(d[3])
        : "r"(a[0]), "r"(a[1]), "r"(a[2]), "r"(a[3]), "r"(b[0]), "r"(b[1]));
}
__device__ __forceinline__ void ldsm4(uint32_t* r, uint32_t addr) {
    asm volatile("ldmatrix.sync.aligned.m8n8.x4.shared.b16 {%0,%1,%2,%3}, [%4];"
        : "=r"(r[0]), "=r"(r[1]), "=r"(r[2]), "=r"(r[3]) : "r"(addr));
}
__device__ __forceinline__ void ldsm4t(uint32_t* r, uint32_t addr) {
    asm volatile("ldmatrix.sync.aligned.m8n8.x4.trans.shared.b16 {%0,%1,%2,%3}, [%4];"
        : "=r"(r[0]), "=r"(r[1]), "=r"(r[2]), "=r"(r[3]) : "r"(addr));
}
__device__ __forceinline__ float ex2(float x) {
    float y; asm("ex2.approx.ftz.f32 %0, %1;" : "=f"(y) : "f"(x)); return y;
}
__device__ __forceinline__ uint32_t smem_u32(const void* p) {
    uint32_t a;
    asm("{ .reg .u64 t; cvta.to.shared.u64 t, %1; cvt.u32.u64 %0, t; }" : "=r"(a) : "l"(p));
    return a;
}
__device__ __forceinline__ void cpasync16(uint32_t dst, const void* src) {
    asm volatile("cp.async.cg.shared.global [%0], [%1], 16;" :: "r"(dst), "l"(src));
}
__device__ __forceinline__ void cpcommit() {
    asm volatile("cp.async.commit_group;" ::: "memory");
}
template <int N> __device__ __forceinline__ void cpwait() {
    asm volatile("cp.async.wait_group %0;" :: "n"(N) : "memory");
}
__device__ __forceinline__ uint32_t packh2(float a, float b) {
    __half2 h = __floats2half2_rn(a, b);
    return *(uint32_t*)&h;
}

// ---------------- fused fp32 -> fp16 conversion (all 5 tensors, one launch) ----------------
// segments (8-elem units): x | Wq(*qscale) | Wk | Wv | Wo
#define CN_X  ((B_SZ * T_SZ * HID) / 8)          // 1048576
#define CN_WQ ((HID * HID) / 8)                  // 524288
#define CN_WK ((512 * HID) / 8)                  // 131072
#define CN_TOT (CN_X + CN_WQ + 2 * CN_WK + CN_WQ)

__global__ void conv_all(const float4* __restrict__ x,  const float4* __restrict__ wq,
                         const float4* __restrict__ wk, const float4* __restrict__ wv,
                         const float4* __restrict__ wo,
                         uint4* __restrict__ xh, uint4* __restrict__ wqkv,
                         uint4* __restrict__ wo_h, float qscale) {
    int i = blockIdx.x * blockDim.x + threadIdx.x;
    if (i >= CN_TOT) return;
    const float4* src; uint4* dst; float sc = 1.f;
    if (i < CN_X) {
        src = x + 2 * (size_t)i; dst = xh + i;
    } else if (i < CN_X + CN_WQ) {
        int j = i - CN_X;
        src = wq + 2 * (size_t)j; dst = wqkv + j; sc = qscale;
    } else if (i < CN_X + CN_WQ + CN_WK) {
        int j = i - CN_X - CN_WQ;
        src = wk + 2 * (size_t)j; dst = wqkv + (size_t)(2048 * HID / 8) + j;
    } else if (i < CN_X + CN_WQ + 2 * CN_WK) {
        int j = i - CN_X - CN_WQ - CN_WK;
        src = wv + 2 * (size_t)j; dst = wqkv + (size_t)(2560 * HID / 8) + j;
    } else {
        int j = i - CN_X - CN_WQ - 2 * CN_WK;
        src = wo + 2 * (size_t)j; dst = wo_h + j;
    }
    float4 a = src[0], b = src[1];
    uint4 o;
    o.x = packh2(a.x * sc, a.y * sc); o.y = packh2(a.z * sc, a.w * sc);
    o.z = packh2(b.x * sc, b.y * sc); o.w = packh2(b.z * sc, b.w * sc);
    *dst = o;
}

// ---------------- RoPE ----------------
__global__ void build_rope_table() {
    int idx = blockIdx.x * blockDim.x + threadIdx.x;
    if (idx >= T_SZ * 64) return;
    int i = idx & 63;
    int t = idx >> 6;
    double inv_freq = pow(10000.0, -(double)i / 64.0);
    double ang = (double)t * inv_freq;
    g_cos[idx] = (float)cos(ang);
    g_sin[idx] = (float)sin(ang);
}

// one kernel: 20 virtual heads = 16 q heads (cols 0-2047) + 4 k heads (cols 2048-2559)
__global__ void rope_all(__half* __restrict__ qkv) {
    int idx = blockIdx.x * blockDim.x + threadIdx.x;
    const int total = B_SZ * T_SZ * 20 * 64;
    if (idx >= total) return;
    int i  = idx & 63;
    int hh = (idx >> 6) % 20;
    int bt = idx / (64 * 20);
    int t  = bt & (T_SZ - 1);
    float c = g_cos[t * 64 + i];
    float s = g_sin[t * 64 + i];
    int col = (hh < 16) ? hh * HD : 2048 + (hh - 16) * HD;
    __half* p = qkv + (size_t)bt * QKV_STR + col + i;
    float x1 = __half2float(p[0]), x2 = __half2float(p[64]);
    p[0]  = __float2half_rn(x1 * c - x2 * s);
    p[64] = __float2half_rn(x2 * c + x1 * s);
}

// ============ fp16 mma GEMM: swizzled smem, 3-stage, 1 sync/chunk, 2 CTA/SM (r15 proven) ============
#define G_TILE_H (128 * 64)
#define G_STAGE_H (2 * G_TILE_H)
#define GEMM_SMEM (3 * G_STAGE_H * 2)       // 98304 bytes

__device__ __forceinline__ uint32_t gswz(int row, int chunk) {
    return (uint32_t)(row * 64 + 8 * (chunk ^ (row & 7)));
}

template <bool OUT_HALF>
__global__ void __launch_bounds__(256, 2)
gemm_h(const __half* __restrict__ A, const __half* __restrict__ Bm,
       void* __restrict__ Cout, int N, int K) {
    extern __shared__ __half hsm[];
    const uint32_t sbase = smem_u32(hsm);
    const int tid  = threadIdx.x;
    const int lane = tid & 31, w = tid >> 5;
    const int wm = w & 1, wn = w >> 1;
    const int g = lane >> 2, tig = lane & 3;
    const int row0 = blockIdx.y * 128, col0 = blockIdx.x * 128;
    const int nchunk = K / 64;

    const int a_row_l = lane & 15, a_ch_l = lane >> 4;
    const int b_n_l = ((lane >> 4) & 1) * 8 + (lane & 7);
    const int b_ch_l = (lane >> 3) & 1;

    float acc[4][4][4];
#pragma unroll
    for (int mt = 0; mt < 4; mt++)
#pragma unroll
        for (int nt = 0; nt < 4; nt++)
#pragma unroll
            for (int j = 0; j < 4; j++) acc[mt][nt][j] = 0.f;

    auto issue = [&](int ci, int st) {
        uint32_t abuf = sbase + (uint32_t)(st * G_STAGE_H) * 2;
        uint32_t bbuf = abuf + G_TILE_H * 2;
#pragma unroll
        for (int j = 0; j < 4; j++) {
            int s = tid + j * 256;
            int r = s >> 3, c = s & 7;
            cpasync16(abuf + gswz(r, c) * 2, A + (size_t)(row0 + r) * K + ci * 64 + c * 8);
            cpasync16(bbuf + gswz(r, c) * 2, Bm + (size_t)(col0 + r) * K + ci * 64 + c * 8);
        }
        cpcommit();
    };

    issue(0, 0);
    if (nchunk > 1) issue(1, 1);

    for (int i = 0; i < nchunk; i++) {
        const int st = i % 3;
        if (i + 1 < nchunk) cpwait<1>();
        else                cpwait<0>();
        __syncthreads();
        if (i + 2 < nchunk) issue(i + 2, (i + 2) % 3);

        uint32_t abuf = sbase + (uint32_t)(st * G_STAGE_H) * 2;
        uint32_t bbuf = abuf + G_TILE_H * 2;
#pragma unroll
        for (int ks = 0; ks < 4; ks++) {
            uint32_t af[4][4];
#pragma unroll
            for (int mt = 0; mt < 4; mt++)
                ldsm4(af[mt], abuf + gswz(wm * 64 + mt * 16 + a_row_l, ks * 2 + a_ch_l) * 2);
            uint32_t bf[2][4];
#pragma unroll
            for (int ntp = 0; ntp < 2; ntp++)
                ldsm4(bf[ntp], bbuf + gswz(wn * 32 + ntp * 16 + b_n_l, ks * 2 + b_ch_l) * 2);
#pragma unroll
            for (int mt = 0; mt < 4; mt++)
#pragma unroll
                for (int nt = 0; nt < 4; nt++)
                    mma_f16(acc[mt][nt], af[mt], &bf[nt >> 1][(nt & 1) * 2]);
        }
    }

#pragma unroll
    for (int mt = 0; mt < 4; mt++) {
        int r = row0 + wm * 64 + mt * 16 + g;
#pragma unroll
        for (int nt = 0; nt < 4; nt++) {
            int c = col0 + wn * 32 + nt * 8 + tig * 2;
            if (OUT_HALF) {
                __half* C = (__half*)Cout;
                *(uint32_t*)(C + (size_t)r * N + c)       = packh2(acc[mt][nt][0], acc[mt][nt][1]);
                *(uint32_t*)(C + (size_t)(r + 8) * N + c) = packh2(acc[mt][nt][2], acc[mt][nt][3]);
            } else {
                float* C = (float*)Cout;
                *(float2*)(C + (size_t)r * N + c)       = make_float2(acc[mt][nt][0], acc[mt][nt][1]);
                *(float2*)(C + (size_t)(r + 8) * N + c) = make_float2(acc[mt][nt][2], acc[mt][nt][3]);
            }
        }
    }
}

// ============ fp16 flash attention: 64-row q tiles, 128 threads, 2 CTA/SM (r15 proven) ============
#define FQ  64
#define FKT 64
#define FHS 136
#define FQO 0
#define FKO(st) (FQ * FHS + (st) * 64 * FHS)
#define FVO(st) (FQ * FHS + 2 * 64 * FHS + (st) * 64 * FHS)
#define FLASH_SMEM_H ((FQ * FHS + 4 * 64 * FHS) * 2)   // 87040 bytes

__global__ void __launch_bounds__(128)
flash_h(const __half* __restrict__ QKVb, __half* __restrict__ Ob) {
    extern __shared__ __half hsm[];
    const uint32_t sbase = smem_u32(hsm);
    const int qt = gridDim.x - 1 - blockIdx.x;   // longest-first
    const int h = blockIdx.y, b = blockIdx.z;
    const int kvh = h >> 2;
    const int tid = threadIdx.x, lane = tid & 31, w = tid >> 5;
    const int g = lane >> 2, tig = lane & 3;
    const int q0 = qt * FQ;
    const int ntile = qt + 1;

    const int a_row_l = lane & 15, a_col_l = (lane >> 4) * 8;
    const int b_n_l = ((lane >> 4) & 1) * 8 + (lane & 7);
    const int b_k_l = ((lane >> 3) & 1) * 8;
    const int v_row_l = ((lane >> 3) & 1) * 8 + (lane & 7);
    const int v_col_l = (lane >> 4) * 8;

    const __half* Kb = QKVb + 2048 + kvh * HD;
    const __half* Vb = Kb + 512;

    auto issueKV = [&](int kt, int st) {
        uint32_t kb = sbase + (uint32_t)FKO(st) * 2;
        uint32_t vb = sbase + (uint32_t)FVO(st) * 2;
#pragma unroll
        for (int j = 0; j < 8; j++) {
            int s = tid + j * 128;
            int r = s >> 4, c8 = (s & 15) << 3;
            size_t row = (size_t)(b * T_SZ + kt * FKT + r) * QKV_STR;
            cpasync16(kb + (uint32_t)(r * FHS + c8) * 2, Kb + row + c8);
            cpasync16(vb + (uint32_t)(r * FHS + c8) * 2, Vb + row + c8);
        }
        cpcommit();
    };

    issueKV(0, 0);

#pragma unroll
    for (int j = 0; j < 8; j++) {
        int s = tid + j * 128;
        int r = s >> 4, c8 = (s & 15) << 3;
        *(uint4*)&hsm[FQO + r * FHS + c8] =
            *(const uint4*)&QKVb[((size_t)(b * T_SZ + q0 + r)) * QKV_STR + h * HD + c8];
    }
    __syncthreads();
    uint32_t qa[8][4];
#pragma unroll
    for (int ks = 0; ks < 8; ks++)
        ldsm4(qa[ks], sbase + (uint32_t)((FQO + (w * 16 + a_row_l) * FHS + ks * 16 + a_col_l)) * 2);

    float O[16][4];
#pragma unroll
    for (int nt = 0; nt < 16; nt++)
#pragma unroll
        for (int j = 0; j < 4; j++) O[nt][j] = 0.f;
    float m0 = -1e30f, m1 = -1e30f, l0 = 0.f, l1 = 0.f;
    const int row_g = q0 + w * 16 + g;

    for (int kt = 0; kt < ntile; kt++) {
        const int k0 = kt * FKT;
        const int st = kt & 1;
        cpwait<0>();
        __syncthreads();
        if (kt + 1 < ntile) issueKV(kt + 1, (kt + 1) & 1);

        const uint32_t kbuf = sbase + (uint32_t)FKO(st) * 2;
        float sfr[8][4];
#pragma unroll
        for (int nt = 0; nt < 8; nt++)
#pragma unroll
            for (int j = 0; j < 4; j++) sfr[nt][j] = 0.f;
#pragma unroll
        for (int ks = 0; ks < 8; ks++) {
#pragma unroll
            for (int ntp = 0; ntp < 4; ntp++) {
                uint32_t bf[4];
                ldsm4(bf, kbuf + (uint32_t)((ntp * 16 + b_n_l) * FHS + ks * 16 + b_k_l) * 2);
                mma_f16(sfr[2 * ntp],     qa[ks], &bf[0]);
                mma_f16(sfr[2 * ntp + 1], qa[ks], &bf[2]);
            }
        }

        if (k0 + FKT - 1 > q0 + w * 16) {
#pragma unroll
            for (int nt = 0; nt < 8; nt++) {
                int c = k0 + nt * 8 + 2 * tig;
                if (c     > row_g)     sfr[nt][0] = -1e30f;
                if (c + 1 > row_g)     sfr[nt][1] = -1e30f;
                if (c     > row_g + 8) sfr[nt][2] = -1e30f;
                if (c + 1 > row_g + 8) sfr[nt][3] = -1e30f;
            }
        }

        float mx0 = -1e30f, mx1 = -1e30f;
#pragma unroll
        for (int nt = 0; nt < 8; nt++) {
            mx0 = fmaxf(mx0, fmaxf(sfr[nt][0], sfr[nt][1]));
            mx1 = fmaxf(mx1, fmaxf(sfr[nt][2], sfr[nt][3]));
        }
        mx0 = fmaxf(mx0, __shfl_xor_sync(0xffffffffu, mx0, 1));
        mx0 = fmaxf(mx0, __shfl_xor_sync(0xffffffffu, mx0, 2));
        mx1 = fmaxf(mx1, __shfl_xor_sync(0xffffffffu, mx1, 1));
        mx1 = fmaxf(mx1, __shfl_xor_sync(0xffffffffu, mx1, 2));
        float mn0 = fmaxf(m0, mx0), mn1 = fmaxf(m1, mx1);
        float al0 = ex2(m0 - mn0), al1 = ex2(m1 - mn1);
        m0 = mn0; m1 = mn1;

        float ps0 = 0.f, ps1 = 0.f;
        uint32_t pa[4][4];
#pragma unroll
        for (int nt = 0; nt < 8; nt++) {
            float p0 = ex2(sfr[nt][0] - mn0);
            float p1 = ex2(sfr[nt][1] - mn0);
            float p2 = ex2(sfr[nt][2] - mn1);
            float p3 = ex2(sfr[nt][3] - mn1);
            ps0 += p0 + p1;
            ps1 += p2 + p3;
            pa[nt >> 1][(nt & 1) * 2 + 0] = packh2(p0, p1);
            pa[nt >> 1][(nt & 1) * 2 + 1] = packh2(p2, p3);
        }
        ps0 += __shfl_xor_sync(0xffffffffu, ps0, 1);
        ps0 += __shfl_xor_sync(0xffffffffu, ps0, 2);
        ps1 += __shfl_xor_sync(0xffffffffu, ps1, 1);
        ps1 += __shfl_xor_sync(0xffffffffu, ps1, 2);
        l0 = l0 * al0 + ps0;
        l1 = l1 * al1 + ps1;
#pragma unroll
        for (int nt = 0; nt < 16; nt++) {
            O[nt][0] *= al0; O[nt][1] *= al0;
            O[nt][2] *= al1; O[nt][3] *= al1;
        }

        const uint32_t vbuf = sbase + (uint32_t)FVO(st) * 2;
#pragma unroll
        for (int ks = 0; ks < 4; ks++) {
#pragma unroll
            for (int ntp = 0; ntp < 8; ntp++) {
                uint32_t bf[4];
                ldsm4t(bf, vbuf + (uint32_t)((ks * 16 + v_row_l) * FHS + ntp * 16 + v_col_l) * 2);
                mma_f16(O[2 * ntp],     pa[ks], &bf[0]);
                mma_f16(O[2 * ntp + 1], pa[ks], &bf[2]);
            }
        }
    }

    float inv0 = 1.f / l0, inv1 = 1.f / l1;
    size_t r0 = (size_t)(b * T_SZ + row_g) * HID + h * HD;
    size_t r1 = (size_t)(b * T_SZ + row_g + 8) * HID + h * HD;
#pragma unroll
    for (int nt = 0; nt < 16; nt++) {
        int c = nt * 8 + 2 * tig;
        *(uint32_t*)&Ob[r0 + c] = packh2(O[nt][0] * inv0, O[nt][1] * inv0);
        *(uint32_t*)&Ob[r1 + c] = packh2(O[nt][2] * inv1, O[nt][3] * inv1);
    }
}

// ---------------- launch ----------------
extern "C" void kernel_launch(void* const* d_in, const int* in_sizes, int n_in,
                              void* d_out, int out_size) {
    const float* x  = (const float*)d_in[0];
    const float* Wq = (const float*)d_in[2];
    const float* Wk = (const float*)d_in[3];
    const float* Wv = (const float*)d_in[4];
    const float* Wo = (const float*)d_in[5];
    float* out = (float*)d_out;

    __half *qkv, *attn, *xh, *wqkv_h, *wo_h;
    cudaGetSymbolAddress((void**)&qkv, g_qkv);
    cudaGetSymbolAddress((void**)&attn, g_attn);
    cudaGetSymbolAddress((void**)&xh, g_xh);
    cudaGetSymbolAddress((void**)&wqkv_h, g_wqkv_h);
    cudaGetSymbolAddress((void**)&wo_h, g_wo_h);

    const int M = B_SZ * T_SZ;  // 4096
    const float qscale = 0.08838834764831843f * 1.4426950408889634f;

    cudaFuncSetAttribute(gemm_h<true>,  cudaFuncAttributeMaxDynamicSharedMemorySize, GEMM_SMEM);
    cudaFuncSetAttribute(gemm_h<false>, cudaFuncAttributeMaxDynamicSharedMemorySize, GEMM_SMEM);
    cudaFuncSetAttribute(flash_h, cudaFuncAttributeMaxDynamicSharedMemorySize, FLASH_SMEM_H);

    // fused fp16 prepass (qscale folded into Wq)
    conv_all<<<(CN_TOT + 255) / 256, 256>>>((const float4*)x, (const float4*)Wq,
                                            (const float4*)Wk, (const float4*)Wv,
                                            (const float4*)Wo,
                                            (uint4*)xh, (uint4*)wqkv_h, (uint4*)wo_h, qscale);

    // fused QKV projection
    gemm_h<true><<<dim3(QKV_STR / 128, M / 128), 256, GEMM_SMEM>>>(xh, wqkv_h, qkv, QKV_STR, HID);

    // RoPE (one launch; q pre-scaled via Wq)
    build_rope_table<<<(T_SZ * 64 + 255) / 256, 256>>>();
    rope_all<<<(M * 20 * 64 + 255) / 256, 256>>>(qkv);

    // attention
    flash_h<<<dim3(T_SZ / FQ, NH, B_SZ), 128, FLASH_SMEM_H>>>(qkv, attn);

    // output projection (float out)
    gemm_h<false><<<dim3(HID / 128, M / 128), 256, GEMM_SMEM>>>(attn, wo_h, out, HID, HID);
}

// round 17
// speedup vs baseline: 1.1974x; 1.0131x over previous
#include <cuda_runtime.h>
#include <cuda_fp16.h>
#include <math.h>
#include <stdint.h>

#define B_SZ 2
#define T_SZ 2048
#define HID  2048
#define NH   16
#define NKV  4
#define HD   128
#define QKV_STR 3072     // fused q|k|v row: q 0-2047, k 2048-2559, v 2560-3071

// ---------------- scratch ----------------
__device__ __half g_qkv[(size_t)B_SZ * T_SZ * QKV_STR];
__device__ __half g_attn[(size_t)B_SZ * T_SZ * HID];
__device__ __half g_xh[(size_t)B_SZ * T_SZ * HID];
__device__ __half g_wqkv_h[(size_t)QKV_STR * HID];
__device__ __half g_wo_h[(size_t)HID * HID];
__device__ float g_cos[T_SZ * 64];
__device__ float g_sin[T_SZ * 64];

// ---------------- helpers ----------------
__device__ __forceinline__ void mma_f16(float* d, const uint32_t* a, const uint32_t* b) {
    asm volatile(
        "mma.sync.aligned.m16n8k16.row.col.f32.f16.f16.f32 "
        "{%0,%1,%2,%3}, {%4,%5,%6,%7}, {%8,%9}, {%0,%1,%2,%3};\n"
        : "+f"(d[0]), "+f"(d[1]), "+f"(d[2]), "+f"(d[3])
        : "r"(a[0]), "r"(a[1]), "r"(a[2]), "r"(a[3]), "r"(b[0]), "r"(b[1]));
}
__device__ __forceinline__ void ldsm4(uint32_t* r, uint32_t addr) {
    asm volatile("ldmatrix.sync.aligned.m8n8.x4.shared.b16 {%0,%1,%2,%3}, [%4];"
        : "=r"(r[0]), "=r"(r[1]), "=r"(r[2]), "=r"(r[3]) : "r"(addr));
}
__device__ __forceinline__ void ldsm4t(uint32_t* r, uint32_t addr) {
    asm volatile("ldmatrix.sync.aligned.m8n8.x4.trans.shared.b16 {%0,%1,%2,%3}, [%4];"
        : "=r"(r[0]), "=r"(r[1]), "=r"(r[2]), "=r"(r[3]) : "r"(addr));
}
__device__ __forceinline__ float ex2(float x) {
    float y; asm("ex2.approx.ftz.f32 %0, %1;" : "=f"(y) : "f"(x)); return y;
}
__device__ __forceinline__ uint32_t smem_u32(const void* p) {
    uint32_t a;
    asm("{ .reg .u64 t; cvta.to.shared.u64 t, %1; cvt.u32.u64 %0, t; }" : "=r"(a) : "l"(p));
    return a;
}
__device__ __forceinline__ void cpasync16(uint32_t dst, const void* src) {
    asm volatile("cp.async.cg.shared.global [%0], [%1], 16;" :: "r"(dst), "l"(src));
}
__device__ __forceinline__ void cpcommit() {
    asm volatile("cp.async.commit_group;" ::: "memory");
}
template <int N> __device__ __forceinline__ void cpwait() {
    asm volatile("cp.async.wait_group %0;" :: "n"(N) : "memory");
}
__device__ __forceinline__ uint32_t packh2(float a, float b) {
    __half2 h = __floats2half2_rn(a, b);
    return *(uint32_t*)&h;
}

// ---------------- fused fp32 -> fp16 conversion (all 5 tensors, one launch) ----------------
#define CN_X  ((B_SZ * T_SZ * HID) / 8)
#define CN_WQ ((HID * HID) / 8)
#define CN_WK ((512 * HID) / 8)
#define CN_TOT (CN_X + CN_WQ + 2 * CN_WK + CN_WQ)

__global__ void conv_all(const float4* __restrict__ x,  const float4* __restrict__ wq,
                         const float4* __restrict__ wk, const float4* __restrict__ wv,
                         const float4* __restrict__ wo,
                         uint4* __restrict__ xh, uint4* __restrict__ wqkv,
                         uint4* __restrict__ wo_h, float qscale) {
    int i = blockIdx.x * blockDim.x + threadIdx.x;
    if (i >= CN_TOT) return;
    const float4* src; uint4* dst; float sc = 1.f;
    if (i < CN_X) {
        src = x + 2 * (size_t)i; dst = xh + i;
    } else if (i < CN_X + CN_WQ) {
        int j = i - CN_X;
        src = wq + 2 * (size_t)j; dst = wqkv + j; sc = qscale;
    } else if (i < CN_X + CN_WQ + CN_WK) {
        int j = i - CN_X - CN_WQ;
        src = wk + 2 * (size_t)j; dst = wqkv + (size_t)(2048 * HID / 8) + j;
    } else if (i < CN_X + CN_WQ + 2 * CN_WK) {
        int j = i - CN_X - CN_WQ - CN_WK;
        src = wv + 2 * (size_t)j; dst = wqkv + (size_t)(2560 * HID / 8) + j;
    } else {
        int j = i - CN_X - CN_WQ - 2 * CN_WK;
        src = wo + 2 * (size_t)j; dst = wo_h + j;
    }
    float4 a = src[0], b = src[1];
    uint4 o;
    o.x = packh2(a.x * sc, a.y * sc); o.y = packh2(a.z * sc, a.w * sc);
    o.z = packh2(b.x * sc, b.y * sc); o.w = packh2(b.z * sc, b.w * sc);
    *dst = o;
}

// ---------------- RoPE table ----------------
__global__ void build_rope_table() {
    int idx = blockIdx.x * blockDim.x + threadIdx.x;
    if (idx >= T_SZ * 64) return;
    int i = idx & 63;
    int t = idx >> 6;
    double inv_freq = pow(10000.0, -(double)i / 64.0);
    double ang = (double)t * inv_freq;
    g_cos[idx] = (float)cos(ang);
    g_sin[idx] = (float)sin(ang);
}

// ============ fp16 mma GEMM, swizzled smem, 3-stage, optional fused RoPE epilogue ============
#define G_TILE_H (128 * 64)
#define G_STAGE_H (2 * G_TILE_H)
#define GEMM_SMEM (3 * G_STAGE_H * 2)       // 98304 bytes

__device__ __forceinline__ uint32_t gswz(int row, int chunk) {
    return (uint32_t)(row * 64 + 8 * (chunk ^ (row & 7)));
}

template <bool OUT_HALF, bool ROPE>
__global__ void __launch_bounds__(256, 2)
gemm_h(const __half* __restrict__ A, const __half* __restrict__ Bm,
       void* __restrict__ Cout, int N, int K) {
    extern __shared__ __half hsm[];
    const uint32_t sbase = smem_u32(hsm);
    const int tid  = threadIdx.x;
    const int lane = tid & 31, w = tid >> 5;
    const int wm = w & 1, wn = w >> 1;
    const int g = lane >> 2, tig = lane & 3;
    const int row0 = blockIdx.y * 128, col0 = blockIdx.x * 128;
    const int nchunk = K / 64;

    const int a_row_l = lane & 15, a_ch_l = lane >> 4;
    const int b_n_l = ((lane >> 4) & 1) * 8 + (lane & 7);
    const int b_ch_l = (lane >> 3) & 1;

    float acc[4][4][4];
#pragma unroll
    for (int mt = 0; mt < 4; mt++)
#pragma unroll
        for (int nt = 0; nt < 4; nt++)
#pragma unroll
            for (int j = 0; j < 4; j++) acc[mt][nt][j] = 0.f;

    auto issue = [&](int ci, int st) {
        uint32_t abuf = sbase + (uint32_t)(st * G_STAGE_H) * 2;
        uint32_t bbuf = abuf + G_TILE_H * 2;
#pragma unroll
        for (int j = 0; j < 4; j++) {
            int s = tid + j * 256;
            int r = s >> 3, c = s & 7;
            cpasync16(abuf + gswz(r, c) * 2, A + (size_t)(row0 + r) * K + ci * 64 + c * 8);
            cpasync16(bbuf + gswz(r, c) * 2, Bm + (size_t)(col0 + r) * K + ci * 64 + c * 8);
        }
        cpcommit();
    };

    issue(0, 0);
    if (nchunk > 1) issue(1, 1);

    for (int i = 0; i < nchunk; i++) {
        const int st = i % 3;
        if (i + 1 < nchunk) cpwait<1>();
        else                cpwait<0>();
        __syncthreads();
        if (i + 2 < nchunk) issue(i + 2, (i + 2) % 3);

        uint32_t abuf = sbase + (uint32_t)(st * G_STAGE_H) * 2;
        uint32_t bbuf = abuf + G_TILE_H * 2;
#pragma unroll
        for (int ks = 0; ks < 4; ks++) {
            uint32_t af[4][4];
#pragma unroll
            for (int mt = 0; mt < 4; mt++)
                ldsm4(af[mt], abuf + gswz(wm * 64 + mt * 16 + a_row_l, ks * 2 + a_ch_l) * 2);
            uint32_t bf[2][4];
#pragma unroll
            for (int ntp = 0; ntp < 2; ntp++)
                ldsm4(bf[ntp], bbuf + gswz(wn * 32 + ntp * 16 + b_n_l, ks * 2 + b_ch_l) * 2);
#pragma unroll
            for (int mt = 0; mt < 4; mt++)
#pragma unroll
                for (int nt = 0; nt < 4; nt++)
                    mma_f16(acc[mt][nt], af[mt], &bf[nt >> 1][(nt & 1) * 2]);
        }
    }

    if (ROPE && col0 < 2560) {
        // Fused RoPE epilogue: stage fp16 tile in smem, rotate (i, i+64), write gmem.
        // Numerics identical to standalone rope kernel (same fp16-rounded inputs, fp32 math).
        __syncthreads();                     // stage buffers no longer needed by mainloop
        __half* stg = hsm;                   // 128 rows x 136 stride = 34816 B
#pragma unroll
        for (int mt = 0; mt < 4; mt++) {
            int r = wm * 64 + mt * 16 + g;
#pragma unroll
            for (int nt = 0; nt < 4; nt++) {
                int c = wn * 32 + nt * 8 + tig * 2;
                *(uint32_t*)&stg[r * 136 + c]       = packh2(acc[mt][nt][0], acc[mt][nt][1]);
                *(uint32_t*)&stg[(r + 8) * 136 + c] = packh2(acc[mt][nt][2], acc[mt][nt][3]);
            }
        }
        __syncthreads();
        __half* C = (__half*)Cout;
#pragma unroll
        for (int j = 0; j < 16; j++) {
            int s = tid + j * 256;           // 4096 units: 128 rows x 32 pair-pairs
            int r = s >> 5, i2 = (s & 31) * 2;
            int t = (row0 + r) & (T_SZ - 1);
            float c0 = g_cos[t * 64 + i2],     s0 = g_sin[t * 64 + i2];
            float c1 = g_cos[t * 64 + i2 + 1], s1 = g_sin[t * 64 + i2 + 1];
            __half2 a = *(__half2*)&stg[r * 136 + i2];
            __half2 bb = *(__half2*)&stg[r * 136 + i2 + 64];
            float x1a = __half2float(a.x),  x1b = __half2float(a.y);
            float x2a = __half2float(bb.x), x2b = __half2float(bb.y);
            size_t base = (size_t)(row0 + r) * N + col0;
            *(uint32_t*)(C + base + i2)      = packh2(x1a * c0 - x2a * s0, x1b * c1 - x2b * s1);
            *(uint32_t*)(C + base + i2 + 64) = packh2(x2a * c0 + x1a * s0, x2b * c1 + x1b * s1);
        }
        return;
    }

#pragma unroll
    for (int mt = 0; mt < 4; mt++) {
        int r = row0 + wm * 64 + mt * 16 + g;
#pragma unroll
        for (int nt = 0; nt < 4; nt++) {
            int c = col0 + wn * 32 + nt * 8 + tig * 2;
            if (OUT_HALF) {
                __half* C = (__half*)Cout;
                *(uint32_t*)(C + (size_t)r * N + c)       = packh2(acc[mt][nt][0], acc[mt][nt][1]);
                *(uint32_t*)(C + (size_t)(r + 8) * N + c) = packh2(acc[mt][nt][2], acc[mt][nt][3]);
            } else {
                float* C = (float*)Cout;
                *(float2*)(C + (size_t)r * N + c)       = make_float2(acc[mt][nt][0], acc[mt][nt][1]);
                *(float2*)(C + (size_t)(r + 8) * N + c) = make_float2(acc[mt][nt][2], acc[mt][nt][3]);
            }
        }
    }
}

// ============ fp16 flash attention: 64-row q tiles, 128 threads, 2 CTA/SM (r15 proven) ============
#define FQ  64
#define FKT 64
#define FHS 136
#define FQO 0
#define FKO(st) (FQ * FHS + (st) * 64 * FHS)
#define FVO(st) (FQ * FHS + 2 * 64 * FHS + (st) * 64 * FHS)
#define FLASH_SMEM_H ((FQ * FHS + 4 * 64 * FHS) * 2)   // 87040 bytes

__global__ void __launch_bounds__(128)
flash_h(const __half* __restrict__ QKVb, __half* __restrict__ Ob) {
    extern __shared__ __half hsm[];
    const uint32_t sbase = smem_u32(hsm);
    const int qt = gridDim.x - 1 - blockIdx.x;   // longest-first
    const int h = blockIdx.y, b = blockIdx.z;
    const int kvh = h >> 2;
    const int tid = threadIdx.x, lane = tid & 31, w = tid >> 5;
    const int g = lane >> 2, tig = lane & 3;
    const int q0 = qt * FQ;
    const int ntile = qt + 1;

    const int a_row_l = lane & 15, a_col_l = (lane >> 4) * 8;
    const int b_n_l = ((lane >> 4) & 1) * 8 + (lane & 7);
    const int b_k_l = ((lane >> 3) & 1) * 8;
    const int v_row_l = ((lane >> 3) & 1) * 8 + (lane & 7);
    const int v_col_l = (lane >> 4) * 8;

    const __half* Kb = QKVb + 2048 + kvh * HD;
    const __half* Vb = Kb + 512;

    auto issueKV = [&](int kt, int st) {
        uint32_t kb = sbase + (uint32_t)FKO(st) * 2;
        uint32_t vb = sbase + (uint32_t)FVO(st) * 2;
#pragma unroll
        for (int j = 0; j < 8; j++) {
            int s = tid + j * 128;
            int r = s >> 4, c8 = (s & 15) << 3;
            size_t row = (size_t)(b * T_SZ + kt * FKT + r) * QKV_STR;
            cpasync16(kb + (uint32_t)(r * FHS + c8) * 2, Kb + row + c8);
            cpasync16(vb + (uint32_t)(r * FHS + c8) * 2, Vb + row + c8);
        }
        cpcommit();
    };

    issueKV(0, 0);

#pragma unroll
    for (int j = 0; j < 8; j++) {
        int s = tid + j * 128;
        int r = s >> 4, c8 = (s & 15) << 3;
        *(uint4*)&hsm[FQO + r * FHS + c8] =
            *(const uint4*)&QKVb[((size_t)(b * T_SZ + q0 + r)) * QKV_STR + h * HD + c8];
    }
    __syncthreads();
    uint32_t qa[8][4];
#pragma unroll
    for (int ks = 0; ks < 8; ks++)
        ldsm4(qa[ks], sbase + (uint32_t)((FQO + (w * 16 + a_row_l) * FHS + ks * 16 + a_col_l)) * 2);

    float O[16][4];
#pragma unroll
    for (int nt = 0; nt < 16; nt++)
#pragma unroll
        for (int j = 0; j < 4; j++) O[nt][j] = 0.f;
    float m0 = -1e30f, m1 = -1e30f, l0 = 0.f, l1 = 0.f;
    const int row_g = q0 + w * 16 + g;

    for (int kt = 0; kt < ntile; kt++) {
        const int k0 = kt * FKT;
        const int st = kt & 1;
        cpwait<0>();
        __syncthreads();
        if (kt + 1 < ntile) issueKV(kt + 1, (kt + 1) & 1);

        const uint32_t kbuf = sbase + (uint32_t)FKO(st) * 2;
        float sfr[8][4];
#pragma unroll
        for (int nt = 0; nt < 8; nt++)
#pragma unroll
            for (int j = 0; j < 4; j++) sfr[nt][j] = 0.f;
#pragma unroll
        for (int ks = 0; ks < 8; ks++) {
#pragma unroll
            for (int ntp = 0; ntp < 4; ntp++) {
                uint32_t bf[4];
                ldsm4(bf, kbuf + (uint32_t)((ntp * 16 + b_n_l) * FHS + ks * 16 + b_k_l) * 2);
                mma_f16(sfr[2 * ntp],     qa[ks], &bf[0]);
                mma_f16(sfr[2 * ntp + 1], qa[ks], &bf[2]);
            }
        }

        if (k0 + FKT - 1 > q0 + w * 16) {
#pragma unroll
            for (int nt = 0; nt < 8; nt++) {
                int c = k0 + nt * 8 + 2 * tig;
                if (c     > row_g)     sfr[nt][0] = -1e30f;
                if (c + 1 > row_g)     sfr[nt][1] = -1e30f;
                if (c     > row_g + 8) sfr[nt][2] = -1e30f;
                if (c + 1 > row_g + 8) sfr[nt][3] = -1e30f;
            }
        }

        float mx0 = -1e30f, mx1 = -1e30f;
#pragma unroll
        for (int nt = 0; nt < 8; nt++) {
            mx0 = fmaxf(mx0, fmaxf(sfr[nt][0], sfr[nt][1]));
            mx1 = fmaxf(mx1, fmaxf(sfr[nt][2], sfr[nt][3]));
        }
        mx0 = fmaxf(mx0, __shfl_xor_sync(0xffffffffu, mx0, 1));
        mx0 = fmaxf(mx0, __shfl_xor_sync(0xffffffffu, mx0, 2));
        mx1 = fmaxf(mx1, __shfl_xor_sync(0xffffffffu, mx1, 1));
        mx1 = fmaxf(mx1, __shfl_xor_sync(0xffffffffu, mx1, 2));
        float mn0 = fmaxf(m0, mx0), mn1 = fmaxf(m1, mx1);
        float al0 = ex2(m0 - mn0), al1 = ex2(m1 - mn1);
        m0 = mn0; m1 = mn1;

        float ps0 = 0.f, ps1 = 0.f;
        uint32_t pa[4][4];
#pragma unroll
        for (int nt = 0; nt < 8; nt++) {
            float p0 = ex2(sfr[nt][0] - mn0);
            float p1 = ex2(sfr[nt][1] - mn0);
            float p2 = ex2(sfr[nt][2] - mn1);
            float p3 = ex2(sfr[nt][3] - mn1);
            ps0 += p0 + p1;
            ps1 += p2 + p3;
            pa[nt >> 1][(nt & 1) * 2 + 0] = packh2(p0, p1);
            pa[nt >> 1][(nt & 1) * 2 + 1] = packh2(p2, p3);
        }
        ps0 += __shfl_xor_sync(0xffffffffu, ps0, 1);
        ps0 += __shfl_xor_sync(0xffffffffu, ps0, 2);
        ps1 += __shfl_xor_sync(0xffffffffu, ps1, 1);
        ps1 += __shfl_xor_sync(0xffffffffu, ps1, 2);
        l0 = l0 * al0 + ps0;
        l1 = l1 * al1 + ps1;
#pragma unroll
        for (int nt = 0; nt < 16; nt++) {
            O[nt][0] *= al0; O[nt][1] *= al0;
            O[nt][2] *= al1; O[nt][3] *= al1;
        }

        const uint32_t vbuf = sbase + (uint32_t)FVO(st) * 2;
#pragma unroll
        for (int ks = 0; ks < 4; ks++) {
#pragma unroll
            for (int ntp = 0; ntp < 8; ntp++) {
                uint32_t bf[4];
                ldsm4t(bf, vbuf + (uint32_t)((ks * 16 + v_row_l) * FHS + ntp * 16 + v_col_l) * 2);
                mma_f16(O[2 * ntp],     pa[ks], &bf[0]);
                mma_f16(O[2 * ntp + 1], pa[ks], &bf[2]);
            }
        }
    }

    float inv0 = 1.f / l0, inv1 = 1.f / l1;
    size_t r0 = (size_t)(b * T_SZ + row_g) * HID + h * HD;
    size_t r1 = (size_t)(b * T_SZ + row_g + 8) * HID + h * HD;
#pragma unroll
    for (int nt = 0; nt < 16; nt++) {
        int c = nt * 8 + 2 * tig;
        *(uint32_t*)&Ob[r0 + c] = packh2(O[nt][0] * inv0, O[nt][1] * inv0);
        *(uint32_t*)&Ob[r1 + c] = packh2(O[nt][2] * inv1, O[nt][3] * inv1);
    }
}

// ---------------- launch ----------------
extern "C" void kernel_launch(void* const* d_in, const int* in_sizes, int n_in,
                              void* d_out, int out_size) {
    const float* x  = (const float*)d_in[0];
    const float* Wq = (const float*)d_in[2];
    const float* Wk = (const float*)d_in[3];
    const float* Wv = (const float*)d_in[4];
    const float* Wo = (const float*)d_in[5];
    float* out = (float*)d_out;

    __half *qkv, *attn, *xh, *wqkv_h, *wo_h;
    cudaGetSymbolAddress((void**)&qkv, g_qkv);
    cudaGetSymbolAddress((void**)&attn, g_attn);
    cudaGetSymbolAddress((void**)&xh, g_xh);
    cudaGetSymbolAddress((void**)&wqkv_h, g_wqkv_h);
    cudaGetSymbolAddress((void**)&wo_h, g_wo_h);

    const int M = B_SZ * T_SZ;  // 4096
    const float qscale = 0.08838834764831843f * 1.4426950408889634f;

    cudaFuncSetAttribute((const void*)gemm_h<true, true>,   cudaFuncAttributeMaxDynamicSharedMemorySize, GEMM_SMEM);
    cudaFuncSetAttribute((const void*)gemm_h<false, false>, cudaFuncAttributeMaxDynamicSharedMemorySize, GEMM_SMEM);
    cudaFuncSetAttribute((const void*)flash_h, cudaFuncAttributeMaxDynamicSharedMemorySize, FLASH_SMEM_H);

    // fused fp16 prepass (qscale folded into Wq) + rope table (needed by gemm epilogue)
    conv_all<<<(CN_TOT + 255) / 256, 256>>>((const float4*)x, (const float4*)Wq,
                                            (const float4*)Wk, (const float4*)Wv,
                                            (const float4*)Wo,
                                            (uint4*)xh, (uint4*)wqkv_h, (uint4*)wo_h, qscale);
    build_rope_table<<<(T_SZ * 64 + 255) / 256, 256>>>();

    // fused QKV projection with RoPE epilogue
    gemm_h<true, true><<<dim3(QKV_STR / 128, M / 128), 256, GEMM_SMEM>>>(xh, wqkv_h, qkv, QKV_STR, HID);

    // attention
    flash_h<<<dim3(T_SZ / FQ, NH, B_SZ), 128, FLASH_SMEM_H>>>(qkv, attn);

    // output projection (float out)
    gemm_h<false, false><<<dim3(HID / 128, M / 128), 256, GEMM_SMEM>>>(attn, wo_h, out, HID, HID);
}